// round 5
// baseline (speedup 1.0000x reference)
#include <cuda_runtime.h>
#include <cuda_bf16.h>
#include <math.h>
#include <stdint.h>

#define B_  32
#define T_  128
#define V_  16000
#define E_  512
#define H_  1024
#define F_  2048
#define G4  4096   // 4*H
#define KC  3072   // 3*H (split-K for H-sized operands)
#define KE  1536   // 3*E (split-K for E-sized operands)
#define NBLK 128   // persistent LSTM blocks

// ---------------- scratch (device globals: no allocation allowed) ----------
__device__ float g_pooled[B_ * F_];
__device__ float g_init[B_ * 2 * H_];
__device__ float g_bsum[G4];
__device__ int   g_idx[B_ * T_];
__device__ float g_xproj[(size_t)B_ * T_ * G4];        // 67 MB
__device__ __nv_bfloat16 g_A2[(size_t)B_ * T_ * KC];   // 25 MB  [hi|hi|lo]
__device__ __nv_bfloat16 g_B2[(size_t)V_ * KC];        // 98 MB  [hi|lo|hi]
__device__ __nv_bfloat16 g_W2[(size_t)G4 * KC];        // 25 MB  [hi|lo|hi]
__device__ __nv_bfloat16 g_E2[(size_t)V_ * KE];        // 49 MB  emb split [hi|hi|lo]
__device__ __nv_bfloat16 g_I2[(size_t)G4 * KE];        // 12.6MB W_ih split [hi|lo|hi]
__device__ __nv_bfloat16 g_A0[B_ * KC];                // h0 split
__device__ unsigned int  g_barcnt;

// ---------------- pooling ----------------------------------------------------
__global__ void pool_kernel(const float* __restrict__ feat) {
    int i = blockIdx.x * blockDim.x + threadIdx.x;
    if (i >= B_ * F_) return;
    const float* p = feat + (size_t)i * 49;
    float s = 0.f;
#pragma unroll
    for (int k = 0; k < 49; k++) s += p[k];
    g_pooled[i] = s * (1.0f / 49.0f);
}

// ---------------- prep ----------------------------------------------------------
__global__ void prep_kernel(const int* __restrict__ reports,
                            const float* __restrict__ b_ih,
                            const float* __restrict__ b_hh) {
    int j = blockIdx.x * blockDim.x + threadIdx.x;
    if (j == 0) g_barcnt = 0u;
    if (j < G4) g_bsum[j] = b_ih[j] + b_hh[j];
    if (j < B_ * T_) g_idx[j] = ((j & (T_ - 1)) == 0) ? 1 : reports[j - 1];
}

// ---------------- small fp32 SGEMM (fc init only) ------------------------------
__global__ void __launch_bounds__(256, 2)
sgemm_fc(const float* __restrict__ A, const float* __restrict__ Bm,
         const float* __restrict__ bias, float* __restrict__ C,
         int M, int N, int K) {
    const int BM = 128, BN = 128, BK = 8;
    __shared__ float As[BK][BM + 4];
    __shared__ float Bs[BK][BN + 4];

    int bm = 0;
    int bn = blockIdx.x * BN;
    int tid = threadIdx.x;
    int lrow = tid >> 1, lk = (tid & 1) * 4;
    int am = bm + lrow;
    bool aval = (am < M);
    const float* Arow = A + (size_t)(aval ? am : 0) * K;
    const float* Brow = Bm + (size_t)(bn + lrow) * K;
    int tx = tid & 15, ty = tid >> 4;

    float acc[8][8];
#pragma unroll
    for (int i = 0; i < 8; i++)
#pragma unroll
        for (int j = 0; j < 8; j++) acc[i][j] = 0.f;

    for (int k0 = 0; k0 < K; k0 += BK) {
        float4 av = aval ? *(const float4*)(Arow + k0 + lk)
                         : make_float4(0.f, 0.f, 0.f, 0.f);
        float4 bvv = *(const float4*)(Brow + k0 + lk);
        As[lk + 0][lrow] = av.x;  As[lk + 1][lrow] = av.y;
        As[lk + 2][lrow] = av.z;  As[lk + 3][lrow] = av.w;
        Bs[lk + 0][lrow] = bvv.x; Bs[lk + 1][lrow] = bvv.y;
        Bs[lk + 2][lrow] = bvv.z; Bs[lk + 3][lrow] = bvv.w;
        __syncthreads();
#pragma unroll
        for (int kk = 0; kk < BK; kk++) {
            float4 a0 = *(const float4*)&As[kk][ty * 8];
            float4 a1 = *(const float4*)&As[kk][ty * 8 + 4];
            float4 b0 = *(const float4*)&Bs[kk][tx * 8];
            float4 b1 = *(const float4*)&Bs[kk][tx * 8 + 4];
            float a[8] = {a0.x, a0.y, a0.z, a0.w, a1.x, a1.y, a1.z, a1.w};
            float b[8] = {b0.x, b0.y, b0.z, b0.w, b1.x, b1.y, b1.z, b1.w};
#pragma unroll
            for (int i = 0; i < 8; i++)
#pragma unroll
                for (int j = 0; j < 8; j++) acc[i][j] += a[i] * b[j];
        }
        __syncthreads();
    }
#pragma unroll
    for (int i = 0; i < 8; i++) {
        int m = bm + ty * 8 + i;
        if (m < M) {
            float* Crow = C + (size_t)m * N + bn + tx * 8;
#pragma unroll
            for (int j = 0; j < 8; j++)
                Crow[j] = acc[i][j] + bias[bn + tx * 8 + j];
        }
    }
}

// ---------------- bf16 split conversions ----------------------------------------
// STYLE 0 (A-side): [hi|hi|lo]   STYLE 1 (B-side): [hi|lo|hi]
template <int SEC, int STYLE>
__global__ void conv_split(const float* __restrict__ S,
                           __nv_bfloat16* __restrict__ D, int total) {
    int i = blockIdx.x * blockDim.x + threadIdx.x;
    if (i >= total) return;
    float x = S[i];
    int m = i / SEC, k = i % SEC;
    __nv_bfloat16 hi = __float2bfloat16(x);
    __nv_bfloat16 lo = __float2bfloat16(x - __bfloat162float(hi));
    __nv_bfloat16* r = D + (size_t)m * (3 * SEC);
    if (STYLE == 0) { r[k] = hi; r[k + SEC] = hi; r[k + 2 * SEC] = lo; }
    else            { r[k] = hi; r[k + SEC] = lo; r[k + 2 * SEC] = hi; }
}

// ---------------- mma helpers ------------------------------------------------------
__device__ __forceinline__ void mma_bf16(float* d, const uint32_t* a,
                                         const uint32_t* b) {
    asm volatile(
        "mma.sync.aligned.m16n8k16.row.col.f32.bf16.bf16.f32 "
        "{%0,%1,%2,%3}, {%4,%5,%6,%7}, {%8,%9}, {%0,%1,%2,%3};"
        : "+f"(d[0]), "+f"(d[1]), "+f"(d[2]), "+f"(d[3])
        : "r"(a[0]), "r"(a[1]), "r"(a[2]), "r"(a[3]), "r"(b[0]), "r"(b[1]));
}
#define XB32(row, kp) (((row) << 4) + ((kp) ^ (((row) & 6) << 1)))

__device__ __forceinline__ float sigmoidf_(float x) {
    return 1.f / (1.f + expf(-x));
}

// ---------------- persistent tensor-core LSTM (512 threads) -----------------------
// Block bi owns 8 hidden units -> 32 gate rows. W slice [32 x 3072] bf16 split
// SMEM-resident. 16 warps: wm = m-half (16 batch rows), wk = k-class (8-way).
// Per step: C[32b x 32g] = h_split @ Wslice^T via mma; 8 partials reduced in smem.
__global__ void __launch_bounds__(512, 1)
lstm_persistent() {
    extern __shared__ char smem[];
    uint32_t* sW = (uint32_t*)smem;                    // 96 slabs x 512 b32 = 192KB
    uint32_t* sA = (uint32_t*)(smem + 196608);         // 2 x 16KB
    float*  Csum = (float*)(smem + 196608);            // overlay, 8*32*33*4 = 33792B

    int tid = threadIdx.x;
    int lane = tid & 31, w = tid >> 5;
    int g = lane >> 2, tig = lane & 3;
    int wm = w >> 3, wk = w & 7;
    int u0 = blockIdx.x * 8;

    // ---- one-time: stage W slice ----
    {
        int r = tid >> 4, e = tid & 15;
        int grow = ((r >> 3) << 10) + u0 + (r & 7);
        const uint4* wrow = (const uint4*)(g_W2 + (size_t)grow * KC);
        int sw = (r & 6) << 1;
#pragma unroll 4
        for (int j = 0; j < 24; j++) {
            int idx = e + j * 16;             // uint4 index within 384
            uint4 v = wrow[idx];
            int s = idx >> 2, q = (idx & 3) * 4;
            *(uint4*)&sW[s * 512 + r * 16 + (q ^ sw)] = v;
        }
    }

    // ---- init c (regs, tid<256) and write h0 split ----
    int cb = tid >> 3, cu = tid & 7;
    int uu = u0 + cu;
    float creg = 0.f;
    if (tid < 256) {
        creg = g_init[cb * 2 * H_ + H_ + uu];
        float h0 = g_init[cb * 2 * H_ + uu];
        __nv_bfloat16 hi = __float2bfloat16(h0);
        __nv_bfloat16 lo = __float2bfloat16(h0 - __bfloat162float(hi));
        __nv_bfloat16* r = g_A0 + cb * KC;
        r[uu] = hi; r[uu + 1024] = hi; r[uu + 2048] = lo;
    }
    __threadfence();

    unsigned epoch = 0;
    volatile unsigned* vb = &g_barcnt;
#define GRIDBAR() do {                                              \
        __syncthreads();                                            \
        epoch++;                                                    \
        if (tid == 0) {                                             \
            atomicAdd(&g_barcnt, 1u);                               \
            while (*vb < epoch * (unsigned)NBLK) {}                 \
            __threadfence();                                        \
        }                                                           \
        __syncthreads();                                            \
    } while (0)

    GRIDBAR();

    int lr = tid >> 4, le = tid & 15;      // A-stage: row 0..31, 2 uint4 each
    int lsw = (lr & 6) << 1;

    for (int t = 0; t < T_; t++) {
        const __nv_bfloat16* Abase =
            (t == 0) ? (g_A0 + lr * KC)
                     : (g_A2 + ((size_t)(lr * T_ + (t - 1))) * KC);
        const uint4* arow = (const uint4*)Abase;

        // prefetch xproj early (DRAM latency off the tail)
        float xp0 = 0.f, xp1 = 0.f, xp2 = 0.f, xp3 = 0.f;
        if (tid < 256) {
            const float* xp = g_xproj + ((size_t)(cb * T_ + t)) * G4 + uu;
            xp0 = xp[0]; xp1 = xp[1024]; xp2 = xp[2048]; xp3 = xp[3072];
        }

        float acc[4][4];
#pragma unroll
        for (int i = 0; i < 4; i++)
#pragma unroll
            for (int q = 0; q < 4; q++) acc[i][q] = 0.f;

        // stage chunk 0
#pragma unroll
        for (int j = 0; j < 2; j++) {
            int cu4 = le + j * 16;
            uint4 v = arow[cu4];
            int s = cu4 >> 2, q = (cu4 & 3) * 4;
            *(uint4*)&sA[s * 512 + lr * 16 + (q ^ lsw)] = v;
        }
        __syncthreads();

        for (int kc = 0; kc < 12; kc++) {
            int p = kc & 1;
            if (kc + 1 < 12) {
                int pb = p ^ 1;
#pragma unroll
                for (int j = 0; j < 2; j++) {
                    int cu4 = le + j * 16;
                    uint4 v = arow[(kc + 1) * 32 + cu4];
                    int s = cu4 >> 2, q = (cu4 & 3) * 4;
                    *(uint4*)&sA[pb * 4096 + s * 512 + lr * 16 + (q ^ lsw)] = v;
                }
            }
            const uint32_t* cA = sA + p * 4096;
#pragma unroll
            for (int jj = 0; jj < 2; jj++) {
                int j16 = jj * 8 + wk;
                int s = j16 >> 1, h = j16 & 1;
                int kp1 = h * 8 + tig, kp2 = kp1 + 4;
                const uint32_t* cAs = cA + s * 512;
                uint32_t af[4];
                int r1 = wm * 16 + g, r2 = r1 + 8;
                af[0] = cAs[XB32(r1, kp1)];
                af[1] = cAs[XB32(r2, kp1)];
                af[2] = cAs[XB32(r1, kp2)];
                af[3] = cAs[XB32(r2, kp2)];
                const uint32_t* cW = sW + (kc * 8 + s) * 512;
#pragma unroll
                for (int nt = 0; nt < 4; nt++) {
                    uint32_t bf[2];
                    bf[0] = cW[XB32(nt * 8 + g, kp1)];
                    bf[1] = cW[XB32(nt * 8 + g, kp2)];
                    mma_bf16(acc[nt], af, bf);
                }
            }
            __syncthreads();
        }

        // write partials (overlay on sA; all mma reads done)
#pragma unroll
        for (int nt = 0; nt < 4; nt++) {
#pragma unroll
            for (int i2 = 0; i2 < 2; i2++) {
                int m = wm * 16 + g + i2 * 8;
                int n = nt * 8 + 2 * tig;
                Csum[(wk * 32 + m) * 33 + n]     = acc[nt][i2 * 2];
                Csum[(wk * 32 + m) * 33 + n + 1] = acc[nt][i2 * 2 + 1];
            }
        }
        __syncthreads();

        if (tid < 256) {
            float gate[4];
#pragma unroll
            for (int g4 = 0; g4 < 4; g4++) {
                int n = g4 * 8 + cu;
                float s = 0.f;
#pragma unroll
                for (int k8 = 0; k8 < 8; k8++)
                    s += Csum[(k8 * 32 + cb) * 33 + n];
                gate[g4] = s;
            }
            gate[0] += xp0; gate[1] += xp1; gate[2] += xp2; gate[3] += xp3;
            float cn = sigmoidf_(gate[1]) * creg + sigmoidf_(gate[0]) * tanhf(gate[2]);
            float hn = sigmoidf_(gate[3]) * tanhf(cn);
            creg = cn;
            __nv_bfloat16 hi = __float2bfloat16(hn);
            __nv_bfloat16 lo = __float2bfloat16(hn - __bfloat162float(hi));
            __nv_bfloat16* r = g_A2 + ((size_t)(cb * T_ + t)) * KC;
            r[uu] = hi; r[uu + 1024] = hi; r[uu + 2048] = lo;
        }
        __threadfence();
        GRIDBAR();
    }
#undef GRIDBAR
}

// ---------------- big bf16 mma GEMM: C[M x N] = A @ B^T + bias ---------------------
// CTA tile 256(m) x 128(n), BK=32, 8 warps (4m x 2n), warp tile 64x64.
// Optional row-gather on A. Register-prefetch double buffer. KTOT % 32 == 0.
template <int KTOT, bool GATHER>
__global__ void __launch_bounds__(256, 1)
mma_gemm_big(const __nv_bfloat16* __restrict__ A2,
             const __nv_bfloat16* __restrict__ B2,
             const float* __restrict__ bias,
             float* __restrict__ C, int ncols,
             const int* __restrict__ ridx) {
    __shared__ uint32_t sA[2][256 * 16];   // 32 KB
    __shared__ uint32_t sB[2][128 * 16];   // 16 KB

    const int NK = KTOT / 32;
    int tid = threadIdx.x;
    int lane = tid & 31, w = tid >> 5;
    int g = lane >> 2, tig = lane & 3;
    int wm = w >> 1, wn = w & 1;

    int m0 = blockIdx.x * 256;
    int n0 = blockIdx.y * 128;

    // A loader: thread -> row m0+tid, 4 uint4 per chunk
    int arowi = GATHER ? ridx[m0 + tid] : (m0 + tid);
    const uint4* pa = (const uint4*)(A2 + (size_t)arowi * KTOT);
    int swa = tid & 6;
    // B loader: row = tid>>1, 2 uint4 per chunk
    int brow = tid >> 1, bhalf = tid & 1;
    const uint4* pb = (const uint4*)(B2 + (size_t)(n0 + brow) * KTOT) + bhalf * 2;
    int swb = brow & 6;
    int bst0 = (brow << 4) + (((bhalf * 4 + 0) ^ swb) << 1);
    int bst1 = (brow << 4) + (((bhalf * 4 + 2) ^ swb) << 1);

    float acc[4][8][4];
#pragma unroll
    for (int i = 0; i < 4; i++)
#pragma unroll
        for (int j = 0; j < 8; j++)
#pragma unroll
            for (int q = 0; q < 4; q++) acc[i][j][q] = 0.f;

    uint4 ra[4], rb[2];
#pragma unroll
    for (int j = 0; j < 4; j++) ra[j] = pa[j];
    rb[0] = pb[0]; rb[1] = pb[1];

    for (int kc = 0; kc < NK; kc++) {
        int p = kc & 1;
#pragma unroll
        for (int j = 0; j < 4; j++)
            *(uint4*)&sA[p][(tid << 4) + (((2 * j) ^ swa) << 1)] = ra[j];
        *(uint4*)&sB[p][bst0] = rb[0];
        *(uint4*)&sB[p][bst1] = rb[1];
        __syncthreads();

        if (kc + 1 < NK) {
#pragma unroll
            for (int j = 0; j < 4; j++) ra[j] = pa[(kc + 1) * 4 + j];
            rb[0] = pb[(kc + 1) * 4 + 0];
            rb[1] = pb[(kc + 1) * 4 + 1];
        }

        const uint32_t* cA = sA[p];
        const uint32_t* cB = sB[p];
#pragma unroll
        for (int ks = 0; ks < 2; ks++) {
            int kp1 = ks * 8 + tig, kp2 = kp1 + 4;
            uint32_t bf[8][2];
#pragma unroll
            for (int nt = 0; nt < 8; nt++) {
                int rbn = wn * 64 + nt * 8 + g;
                bf[nt][0] = cB[XB32(rbn, kp1)];
                bf[nt][1] = cB[XB32(rbn, kp2)];
            }
#pragma unroll
            for (int mt = 0; mt < 4; mt++) {
                int r1 = wm * 64 + mt * 16 + g, r2 = r1 + 8;
                uint32_t af[4];
                af[0] = cA[XB32(r1, kp1)];
                af[1] = cA[XB32(r2, kp1)];
                af[2] = cA[XB32(r1, kp2)];
                af[3] = cA[XB32(r2, kp2)];
#pragma unroll
                for (int nt = 0; nt < 8; nt++)
                    mma_bf16(acc[mt][nt], af, bf[nt]);
            }
        }
        __syncthreads();
    }

#pragma unroll
    for (int mt = 0; mt < 4; mt++) {
#pragma unroll
        for (int i2 = 0; i2 < 2; i2++) {
            int row = m0 + wm * 64 + mt * 16 + g + i2 * 8;
            float* crow = C + (size_t)row * ncols;
#pragma unroll
            for (int nt = 0; nt < 8; nt++) {
                int col = n0 + wn * 64 + nt * 8 + 2 * tig;
                float b0 = __ldg(&bias[col]);
                float b1 = __ldg(&bias[col + 1]);
                crow[col]     = acc[mt][nt][i2 * 2]     + b0;
                crow[col + 1] = acc[mt][nt][i2 * 2 + 1] + b1;
            }
        }
    }
}

// ---------------- launcher ---------------------------------------------------------
extern "C" void kernel_launch(void* const* d_in, const int* in_sizes, int n_in,
                              void* d_out, int out_size) {
    const float* features = (const float*)d_in[0];
    const int*   reports  = (const int*)d_in[1];
    const float* fc_W     = (const float*)d_in[2];
    const float* fc_b     = (const float*)d_in[3];
    const float* emb      = (const float*)d_in[4];
    const float* W_ih     = (const float*)d_in[5];
    const float* W_hh     = (const float*)d_in[6];
    const float* b_ih     = (const float*)d_in[7];
    const float* b_hh     = (const float*)d_in[8];
    const float* Wv       = (const float*)d_in[9];
    const float* bv       = (const float*)d_in[10];
    float* out = (float*)d_out;

    float *pooled_p, *init_p, *xproj_p, *bsum_p;
    __nv_bfloat16 *A2_p, *B2_p, *W2_p, *E2_p, *I2_p;
    int* idx_p;
    cudaGetSymbolAddress((void**)&pooled_p, g_pooled);
    cudaGetSymbolAddress((void**)&init_p,   g_init);
    cudaGetSymbolAddress((void**)&xproj_p,  g_xproj);
    cudaGetSymbolAddress((void**)&bsum_p,   g_bsum);
    cudaGetSymbolAddress((void**)&idx_p,    g_idx);
    cudaGetSymbolAddress((void**)&A2_p,     g_A2);
    cudaGetSymbolAddress((void**)&B2_p,     g_B2);
    cudaGetSymbolAddress((void**)&W2_p,     g_W2);
    cudaGetSymbolAddress((void**)&E2_p,     g_E2);
    cudaGetSymbolAddress((void**)&I2_p,     g_I2);

    cudaFuncSetAttribute(lstm_persistent,
                         cudaFuncAttributeMaxDynamicSharedMemorySize, 230400);

    // 1) pooling
    pool_kernel<<<(B_ * F_ + 255) / 256, 256>>>(features);

    // 2) fc init
    sgemm_fc<<<(2 * H_) / 128, 256>>>(pooled_p, fc_W, fc_b, init_p, B_, 2 * H_, F_);

    // 3) prep
    prep_kernel<<<(B_ * H_ + 255) / 256, 256>>>(reports, b_ih, b_hh);

    // 4) weight / embedding splits
    conv_split<1024, 1><<<(V_ * H_ + 255) / 256, 256>>>(Wv, B2_p, V_ * H_);
    conv_split<1024, 1><<<(G4 * H_ + 255) / 256, 256>>>(W_hh, W2_p, G4 * H_);
    conv_split<512, 0><<<(V_ * E_ + 255) / 256, 256>>>(emb, E2_p, V_ * E_);
    conv_split<512, 1><<<(G4 * E_ + 255) / 256, 256>>>(W_ih, I2_p, G4 * E_);

    // 5) xproj = emb[idx] @ W_ih^T + bsum   (tensor cores, gathered A)
    mma_gemm_big<KE, true><<<dim3((B_ * T_) / 256, G4 / 128), 256>>>(
        E2_p, I2_p, bsum_p, xproj_p, G4, idx_p);

    // 6) persistent tensor-core LSTM (all 128 steps)
    lstm_persistent<<<NBLK, 512, 230400>>>();

    // 7) output projection (tensor cores)
    mma_gemm_big<KC, false><<<dim3((B_ * T_) / 256, V_ / 128), 256>>>(
        A2_p, B2_p, bv, out, V_, nullptr);
}

// round 6
// speedup vs baseline: 1.0603x; 1.0603x over previous
#include <cuda_runtime.h>
#include <cuda_bf16.h>
#include <math.h>
#include <stdint.h>

#define B_  32
#define T_  128
#define V_  16000
#define E_  512
#define H_  1024
#define F_  2048
#define G4  4096   // 4*H
#define KC  3072   // 3*H (split-K for H-sized operands)
#define KE  1536   // 3*E (split-K for E-sized operands)
#define NBLK 128   // persistent LSTM blocks

// ---------------- scratch (device globals: no allocation allowed) ----------
__device__ float g_pooled[B_ * F_];
__device__ float g_init[B_ * 2 * H_];
__device__ float g_bsum[G4];
__device__ int   g_idx[B_ * T_];
__device__ float g_xproj[(size_t)B_ * T_ * G4];        // 67 MB
__device__ __nv_bfloat16 g_A2[(size_t)B_ * T_ * KC];   // 25 MB  [hi|hi|lo]
__device__ __nv_bfloat16 g_B2[(size_t)V_ * KC];        // 98 MB  [hi|lo|hi]
__device__ __nv_bfloat16 g_W2[(size_t)G4 * KC];        // 25 MB  [hi|lo|hi]
__device__ __nv_bfloat16 g_E2[(size_t)V_ * KE];        // 49 MB  [hi|hi|lo]
__device__ __nv_bfloat16 g_I2[(size_t)G4 * KE];        // 12.6MB [hi|lo|hi]
__device__ __nv_bfloat16 g_A0[B_ * KC];                // h0 split
__device__ unsigned int  g_barcnt;

// ---------------- fused bf16 split conversions (ONE launch) -------------------
// Regions: [0, V*H)       Wv   -> g_B2  style B [hi|lo|hi], SEC=1024
//          [+, +G4*H)     W_hh -> g_W2  style B, SEC=1024
//          [+, +V*E)      emb  -> g_E2  style A [hi|hi|lo], SEC=512
//          [+, +G4*E)     W_ih -> g_I2  style B, SEC=512
#define NW_  (V_ * H_)
#define NWH  (G4 * H_)
#define NEM  (V_ * E_)
#define NWI  (G4 * E_)
__global__ void conv_all_kernel(const float* __restrict__ Wv,
                                const float* __restrict__ W_hh,
                                const float* __restrict__ emb,
                                const float* __restrict__ W_ih) {
    int i = blockIdx.x * blockDim.x + threadIdx.x;
    const float* S;
    __nv_bfloat16* D;
    int li, sec, style;
    if (i < NW_) {
        S = Wv; D = g_B2; li = i; sec = 1024; style = 1;
    } else if (i < NW_ + NWH) {
        S = W_hh; D = g_W2; li = i - NW_; sec = 1024; style = 1;
    } else if (i < NW_ + NWH + NEM) {
        S = emb; D = g_E2; li = i - NW_ - NWH; sec = 512; style = 0;
    } else if (i < NW_ + NWH + NEM + NWI) {
        S = W_ih; D = g_I2; li = i - NW_ - NWH - NEM; sec = 512; style = 1;
    } else return;
    float x = S[li];
    int m = (sec == 1024) ? (li >> 10) : (li >> 9);
    int k = li & (sec - 1);
    __nv_bfloat16 hi = __float2bfloat16(x);
    __nv_bfloat16 lo = __float2bfloat16(x - __bfloat162float(hi));
    __nv_bfloat16* r = D + (size_t)m * (3 * sec);
    if (style == 0) { r[k] = hi; r[k + sec] = hi; r[k + 2 * sec] = lo; }
    else            { r[k] = hi; r[k + sec] = lo; r[k + 2 * sec] = hi; }
}

// ---------------- pooling ----------------------------------------------------
__global__ void pool_kernel(const float* __restrict__ feat) {
    int i = blockIdx.x * blockDim.x + threadIdx.x;
    if (i >= B_ * F_) return;
    const float* p = feat + (size_t)i * 49;
    float s = 0.f;
#pragma unroll
    for (int k = 0; k < 49; k++) s += p[k];
    g_pooled[i] = s * (1.0f / 49.0f);
}

// ---------------- small fp32 SGEMM (fc init only) ------------------------------
__global__ void __launch_bounds__(256, 2)
sgemm_fc(const float* __restrict__ A, const float* __restrict__ Bm,
         const float* __restrict__ bias, float* __restrict__ C,
         int M, int N, int K) {
    const int BN = 128, BK = 8;
    __shared__ float As[BK][128 + 4];
    __shared__ float Bs[BK][BN + 4];

    int bn = blockIdx.x * BN;
    int tid = threadIdx.x;
    int lrow = tid >> 1, lk = (tid & 1) * 4;
    bool aval = (lrow < M);
    const float* Arow = A + (size_t)(aval ? lrow : 0) * K;
    const float* Brow = Bm + (size_t)(bn + lrow) * K;
    int tx = tid & 15, ty = tid >> 4;

    float acc[8][8];
#pragma unroll
    for (int i = 0; i < 8; i++)
#pragma unroll
        for (int j = 0; j < 8; j++) acc[i][j] = 0.f;

    for (int k0 = 0; k0 < K; k0 += BK) {
        float4 av = aval ? *(const float4*)(Arow + k0 + lk)
                         : make_float4(0.f, 0.f, 0.f, 0.f);
        float4 bvv = *(const float4*)(Brow + k0 + lk);
        As[lk + 0][lrow] = av.x;  As[lk + 1][lrow] = av.y;
        As[lk + 2][lrow] = av.z;  As[lk + 3][lrow] = av.w;
        Bs[lk + 0][lrow] = bvv.x; Bs[lk + 1][lrow] = bvv.y;
        Bs[lk + 2][lrow] = bvv.z; Bs[lk + 3][lrow] = bvv.w;
        __syncthreads();
#pragma unroll
        for (int kk = 0; kk < BK; kk++) {
            float4 a0 = *(const float4*)&As[kk][ty * 8];
            float4 a1 = *(const float4*)&As[kk][ty * 8 + 4];
            float4 b0 = *(const float4*)&Bs[kk][tx * 8];
            float4 b1 = *(const float4*)&Bs[kk][tx * 8 + 4];
            float a[8] = {a0.x, a0.y, a0.z, a0.w, a1.x, a1.y, a1.z, a1.w};
            float b[8] = {b0.x, b0.y, b0.z, b0.w, b1.x, b1.y, b1.z, b1.w};
#pragma unroll
            for (int i = 0; i < 8; i++)
#pragma unroll
                for (int j = 0; j < 8; j++) acc[i][j] += a[i] * b[j];
        }
        __syncthreads();
    }
#pragma unroll
    for (int i = 0; i < 8; i++) {
        int m = ty * 8 + i;
        if (m < M) {
            float* Crow = C + (size_t)m * N + bn + tx * 8;
#pragma unroll
            for (int j = 0; j < 8; j++)
                Crow[j] = acc[i][j] + bias[bn + tx * 8 + j];
        }
    }
}

// ---------------- prep ----------------------------------------------------------
__global__ void prep_kernel(const int* __restrict__ reports,
                            const float* __restrict__ b_ih,
                            const float* __restrict__ b_hh) {
    int j = blockIdx.x * blockDim.x + threadIdx.x;
    if (j == 0) g_barcnt = 0u;
    if (j < G4) g_bsum[j] = b_ih[j] + b_hh[j];
    if (j < B_ * T_) g_idx[j] = ((j & (T_ - 1)) == 0) ? 1 : reports[j - 1];
}

// ---------------- mma helpers ------------------------------------------------------
__device__ __forceinline__ void mma_bf16(float* d, const uint32_t* a,
                                         const uint32_t* b) {
    asm volatile(
        "mma.sync.aligned.m16n8k16.row.col.f32.bf16.bf16.f32 "
        "{%0,%1,%2,%3}, {%4,%5,%6,%7}, {%8,%9}, {%0,%1,%2,%3};"
        : "+f"(d[0]), "+f"(d[1]), "+f"(d[2]), "+f"(d[3])
        : "r"(a[0]), "r"(a[1]), "r"(a[2]), "r"(a[3]), "r"(b[0]), "r"(b[1]));
}
#define XB32(row, kp) (((row) << 4) + ((kp) ^ (((row) & 6) << 1)))

__device__ __forceinline__ float sigmoidf_(float x) {
    return 1.f / (1.f + expf(-x));
}

// ---------------- 128x128 bf16 mma GEMM (xproj + output proj) -----------------------
// C[m][n] = sum_k A[rowidx(m)][k] * B[n][k] + bias[n]; KTOT % 32 == 0.
template <int KTOT, bool GATHER>
__global__ void __launch_bounds__(256, 2)
mma_gemm_nt(const __nv_bfloat16* __restrict__ A2,
            const __nv_bfloat16* __restrict__ B2,
            const float* __restrict__ bias,
            float* __restrict__ C, int ncols,
            const int* __restrict__ ridx) {
    __shared__ uint32_t sA[2][128 * 16];
    __shared__ uint32_t sB[2][128 * 16];

    const int NK = KTOT / 32;
    int tid = threadIdx.x;
    int lane = tid & 31, w = tid >> 5;
    int g = lane >> 2, tig = lane & 3;
    int wm = w >> 2, wn = w & 3;

    int m0 = blockIdx.x * 128;
    int n0 = blockIdx.y * 128;

    int lrow = tid >> 1;
    int lhalf = tid & 1;
    int ar = GATHER ? ridx[m0 + lrow] : (m0 + lrow);
    const uint4* pa = (const uint4*)(A2 + (size_t)ar * KTOT) + lhalf * 2;
    const uint4* pb = (const uint4*)(B2 + (size_t)(n0 + lrow) * KTOT) + lhalf * 2;
    int sw = lrow & 6;
    int st0 = (lrow << 4) + (((lhalf * 4 + 0) ^ sw) << 1);
    int st1 = (lrow << 4) + (((lhalf * 4 + 2) ^ sw) << 1);

    float acc[4][4][4];
#pragma unroll
    for (int i = 0; i < 4; i++)
#pragma unroll
        for (int j = 0; j < 4; j++)
#pragma unroll
            for (int q = 0; q < 4; q++) acc[i][j][q] = 0.f;

    uint4 ra0 = pa[0], ra1 = pa[1];
    uint4 rb0 = pb[0], rb1 = pb[1];

    for (int kc = 0; kc < NK; kc++) {
        int p = kc & 1;
        *(uint4*)&sA[p][st0] = ra0;
        *(uint4*)&sA[p][st1] = ra1;
        *(uint4*)&sB[p][st0] = rb0;
        *(uint4*)&sB[p][st1] = rb1;
        __syncthreads();

        if (kc + 1 < NK) {
            ra0 = pa[(kc + 1) * 4 + 0]; ra1 = pa[(kc + 1) * 4 + 1];
            rb0 = pb[(kc + 1) * 4 + 0]; rb1 = pb[(kc + 1) * 4 + 1];
        }

        const uint32_t* cA = sA[p];
        const uint32_t* cB = sB[p];
#pragma unroll
        for (int ks = 0; ks < 2; ks++) {
            int kp1 = ks * 8 + tig;
            int kp2 = kp1 + 4;
            uint32_t bf[4][2];
#pragma unroll
            for (int nt = 0; nt < 4; nt++) {
                int rb = wn * 32 + nt * 8 + g;
                bf[nt][0] = cB[XB32(rb, kp1)];
                bf[nt][1] = cB[XB32(rb, kp2)];
            }
#pragma unroll
            for (int mt = 0; mt < 4; mt++) {
                int r1 = wm * 64 + mt * 16 + g;
                int r2 = r1 + 8;
                uint32_t af[4];
                af[0] = cA[XB32(r1, kp1)];
                af[1] = cA[XB32(r2, kp1)];
                af[2] = cA[XB32(r1, kp2)];
                af[3] = cA[XB32(r2, kp2)];
#pragma unroll
                for (int nt = 0; nt < 4; nt++)
                    mma_bf16(acc[mt][nt], af, bf[nt]);
            }
        }
        __syncthreads();
    }

#pragma unroll
    for (int mt = 0; mt < 4; mt++) {
#pragma unroll
        for (int i2 = 0; i2 < 2; i2++) {
            int row = m0 + wm * 64 + mt * 16 + g + i2 * 8;
            float* crow = C + (size_t)row * ncols;
#pragma unroll
            for (int nt = 0; nt < 4; nt++) {
                int col = n0 + wn * 32 + nt * 8 + 2 * tig;
                float b0 = __ldg(&bias[col]);
                float b1 = __ldg(&bias[col + 1]);
                crow[col]     = acc[mt][nt][i2 * 2]     + b0;
                crow[col + 1] = acc[mt][nt][i2 * 2 + 1] + b1;
            }
        }
    }
}

// ---------------- persistent tensor-core LSTM (256 threads, R4 config) -----------
__global__ void __launch_bounds__(256, 1)
lstm_persistent() {
    extern __shared__ char smem[];
    uint32_t* sW = (uint32_t*)smem;                    // 96 slabs x 512 b32 = 192KB
    uint32_t* sA = (uint32_t*)(smem + 196608);         // 2 x 16KB
    float*  Csum = (float*)(smem + 196608);            // overlay (16.9KB)

    int tid = threadIdx.x;
    int lane = tid & 31, w = tid >> 5;
    int g = lane >> 2, tig = lane & 3;
    int wm = w >> 2, wk = w & 3;
    int u0 = blockIdx.x * 8;

    // ---- one-time: stage W slice ----
    {
        int r = tid >> 3, e = tid & 7;
        int grow = ((r >> 3) << 10) + u0 + (r & 7);
        const uint4* wrow = (const uint4*)(g_W2 + (size_t)grow * KC);
        int sw = (r & 6) << 1;
#pragma unroll 4
        for (int j = 0; j < 48; j++) {
            int idx = e + j * 8;
            uint4 v = wrow[idx];
            int s = idx >> 2, q = (idx & 3) * 4;
            *(uint4*)&sW[s * 512 + r * 16 + (q ^ sw)] = v;
        }
    }

    // ---- init c (regs) and write h0 split ----
    int cb = tid >> 3, cu = tid & 7;
    int uu = u0 + cu;
    float creg = g_init[cb * 2 * H_ + H_ + uu];
    {
        float h0 = g_init[cb * 2 * H_ + uu];
        __nv_bfloat16 hi = __float2bfloat16(h0);
        __nv_bfloat16 lo = __float2bfloat16(h0 - __bfloat162float(hi));
        __nv_bfloat16* r = g_A0 + cb * KC;
        r[uu] = hi; r[uu + 1024] = hi; r[uu + 2048] = lo;
    }
    __threadfence();

    unsigned epoch = 0;
    volatile unsigned* vb = &g_barcnt;
#define GRIDBAR() do {                                              \
        __syncthreads();                                            \
        epoch++;                                                    \
        if (tid == 0) {                                             \
            atomicAdd(&g_barcnt, 1u);                               \
            while (*vb < epoch * (unsigned)NBLK) __nanosleep(64);   \
            __threadfence();                                        \
        }                                                           \
        __syncthreads();                                            \
    } while (0)

    GRIDBAR();

    int lr = tid >> 3, le = tid & 7;
    int lsw = (lr & 6) << 1;

    for (int t = 0; t < T_; t++) {
        const __nv_bfloat16* Abase =
            (t == 0) ? (g_A0 + lr * KC)
                     : (g_A2 + ((size_t)(lr * T_ + (t - 1))) * KC);
        const uint4* arow = (const uint4*)Abase;

        // prefetch xproj (DRAM latency off the serial tail)
        const float* xp = g_xproj + ((size_t)(cb * T_ + t)) * G4 + uu;
        float xp0 = xp[0], xp1 = xp[1024], xp2 = xp[2048], xp3 = xp[3072];

        float acc[4][4];
#pragma unroll
        for (int i = 0; i < 4; i++)
#pragma unroll
            for (int q = 0; q < 4; q++) acc[i][q] = 0.f;

#pragma unroll
        for (int j = 0; j < 4; j++) {
            int cu4 = le + j * 8;
            uint4 v = arow[cu4];
            int s = cu4 >> 2, q = (cu4 & 3) * 4;
            *(uint4*)&sA[s * 512 + lr * 16 + (q ^ lsw)] = v;
        }
        __syncthreads();

        for (int kc = 0; kc < 12; kc++) {
            int p = kc & 1;
            if (kc + 1 < 12) {
                int pb = p ^ 1;
#pragma unroll
                for (int j = 0; j < 4; j++) {
                    int cu4 = le + j * 8;
                    uint4 v = arow[(kc + 1) * 32 + cu4];
                    int s = cu4 >> 2, q = (cu4 & 3) * 4;
                    *(uint4*)&sA[pb * 4096 + s * 512 + lr * 16 + (q ^ lsw)] = v;
                }
            }
            const uint32_t* cA = sA + p * 4096;
#pragma unroll
            for (int jj = 0; jj < 4; jj++) {
                int j16 = jj * 4 + wk;
                int s = j16 >> 1, h = j16 & 1;
                int kp1 = h * 8 + tig, kp2 = kp1 + 4;
                int ab = s * 512;
                uint32_t af[4];
                int r1 = wm * 16 + g, r2 = r1 + 8;
                af[0] = cA[ab + XB32(r1, kp1)];
                af[1] = cA[ab + XB32(r2, kp1)];
                af[2] = cA[ab + XB32(r1, kp2)];
                af[3] = cA[ab + XB32(r2, kp2)];
                const uint32_t* cW = sW + (kc * 8 + s) * 512;
#pragma unroll
                for (int nt = 0; nt < 4; nt++) {
                    uint32_t bf[2];
                    bf[0] = cW[XB32(nt * 8 + g, kp1)];
                    bf[1] = cW[XB32(nt * 8 + g, kp2)];
                    mma_bf16(acc[nt], af, bf);
                }
            }
            __syncthreads();
        }

#pragma unroll
        for (int nt = 0; nt < 4; nt++) {
#pragma unroll
            for (int i2 = 0; i2 < 2; i2++) {
                int m = wm * 16 + g + i2 * 8;
                int n = nt * 8 + 2 * tig;
                Csum[(wk * 32 + m) * 33 + n]     = acc[nt][i2 * 2];
                Csum[(wk * 32 + m) * 33 + n + 1] = acc[nt][i2 * 2 + 1];
            }
        }
        __syncthreads();

        {
            float gate[4];
#pragma unroll
            for (int g4 = 0; g4 < 4; g4++) {
                int n = g4 * 8 + cu;
                gate[g4] = Csum[(0 * 32 + cb) * 33 + n] + Csum[(1 * 32 + cb) * 33 + n]
                         + Csum[(2 * 32 + cb) * 33 + n] + Csum[(3 * 32 + cb) * 33 + n];
            }
            gate[0] += xp0; gate[1] += xp1; gate[2] += xp2; gate[3] += xp3;
            float cn = sigmoidf_(gate[1]) * creg + sigmoidf_(gate[0]) * tanhf(gate[2]);
            float hn = sigmoidf_(gate[3]) * tanhf(cn);
            creg = cn;
            __nv_bfloat16 hi = __float2bfloat16(hn);
            __nv_bfloat16 lo = __float2bfloat16(hn - __bfloat162float(hi));
            __nv_bfloat16* r = g_A2 + ((size_t)(cb * T_ + t)) * KC;
            r[uu] = hi; r[uu + 1024] = hi; r[uu + 2048] = lo;
        }
        __threadfence();
        GRIDBAR();
    }
#undef GRIDBAR
}

// ---------------- launcher ---------------------------------------------------------
extern "C" void kernel_launch(void* const* d_in, const int* in_sizes, int n_in,
                              void* d_out, int out_size) {
    const float* features = (const float*)d_in[0];
    const int*   reports  = (const int*)d_in[1];
    const float* fc_W     = (const float*)d_in[2];
    const float* fc_b     = (const float*)d_in[3];
    const float* emb      = (const float*)d_in[4];
    const float* W_ih     = (const float*)d_in[5];
    const float* W_hh     = (const float*)d_in[6];
    const float* b_ih     = (const float*)d_in[7];
    const float* b_hh     = (const float*)d_in[8];
    const float* Wv       = (const float*)d_in[9];
    const float* bv       = (const float*)d_in[10];
    float* out = (float*)d_out;

    float *pooled_p, *init_p, *xproj_p, *bsum_p;
    __nv_bfloat16 *A2_p, *B2_p, *E2_p, *I2_p;
    int* idx_p;
    cudaGetSymbolAddress((void**)&pooled_p, g_pooled);
    cudaGetSymbolAddress((void**)&init_p,   g_init);
    cudaGetSymbolAddress((void**)&xproj_p,  g_xproj);
    cudaGetSymbolAddress((void**)&bsum_p,   g_bsum);
    cudaGetSymbolAddress((void**)&idx_p,    g_idx);
    cudaGetSymbolAddress((void**)&A2_p,     g_A2);
    cudaGetSymbolAddress((void**)&B2_p,     g_B2);
    cudaGetSymbolAddress((void**)&E2_p,     g_E2);
    cudaGetSymbolAddress((void**)&I2_p,     g_I2);

    cudaFuncSetAttribute(lstm_persistent,
                         cudaFuncAttributeMaxDynamicSharedMemorySize, 229376);

    // launch #1: fused bf16 splits (independent of everything else)
    int convN = NW_ + NWH + NEM + NWI;
    conv_all_kernel<<<(convN + 255) / 256, 256>>>(Wv, W_hh, emb, W_ih);

    // #2: pooling
    pool_kernel<<<(B_ * F_ + 255) / 256, 256>>>(features);

    // #3: fc init
    sgemm_fc<<<(2 * H_) / 128, 256>>>(pooled_p, fc_W, fc_b, init_p, B_, 2 * H_, F_);

    // #4: prep
    prep_kernel<<<(B_ * H_ + 255) / 256, 256>>>(reports, b_ih, b_hh);

    // #5: xproj = emb[idx] @ W_ih^T + bsum (tensor cores, gathered A)
    mma_gemm_nt<KE, true><<<dim3((B_ * T_) / 128, G4 / 128), 256>>>(
        E2_p, I2_p, bsum_p, xproj_p, G4, idx_p);

    // #6: persistent tensor-core LSTM  <-- ncu -s 5 -c 1 captures THIS
    lstm_persistent<<<NBLK, 256, 229376>>>();

    // #7: output projection
    mma_gemm_nt<KC, false><<<dim3((B_ * T_) / 128, V_ / 128), 256>>>(
        A2_p, B2_p, bv, out, V_, nullptr);
}

// round 7
// speedup vs baseline: 1.2639x; 1.1920x over previous
#include <cuda_runtime.h>
#include <cuda_bf16.h>
#include <math.h>
#include <stdint.h>

#define B_  32
#define T_  128
#define V_  16000
#define E_  512
#define H_  1024
#define F_  2048
#define G4  4096   // 4*H
#define KC  3072   // 3*H (split-K for H-sized operands)
#define KE  1536   // 3*E (split-K for E-sized operands)
#define NBLK 128   // persistent LSTM blocks

// ---------------- scratch (device globals: no allocation allowed) ----------
__device__ float g_pooled[B_ * F_];
__device__ float g_bsum[G4];
__device__ int   g_idx[B_ * T_];
__device__ float g_xproj[(size_t)B_ * T_ * G4];        // 67 MB
__device__ __nv_bfloat16 g_A2[(size_t)B_ * T_ * KC];   // 25 MB  [hi|hi|lo]
__device__ __nv_bfloat16 g_B2[(size_t)V_ * KC];        // 98 MB  [hi|lo|hi]
__device__ __nv_bfloat16 g_W2[(size_t)G4 * KC];        // 25 MB  [hi|lo|hi]
__device__ __nv_bfloat16 g_E2[(size_t)V_ * KE];        // 49 MB  [hi|hi|lo]
__device__ __nv_bfloat16 g_I2[(size_t)G4 * KE];        // 12.6MB [hi|lo|hi]
__device__ __nv_bfloat16 g_A0[B_ * KC];                // h0 split
__device__ unsigned int  g_barcnt;

// ---------------- fused bf16 split conversions (launch #1) --------------------
#define NW_  (V_ * H_)
#define NWH  (G4 * H_)
#define NEM  (V_ * E_)
#define NWI  (G4 * E_)
__global__ void conv_all_kernel(const float* __restrict__ Wv,
                                const float* __restrict__ W_hh,
                                const float* __restrict__ emb,
                                const float* __restrict__ W_ih) {
    int i = blockIdx.x * blockDim.x + threadIdx.x;
    const float* S;
    __nv_bfloat16* D;
    int li, sec, style;
    if (i < NW_) {
        S = Wv; D = g_B2; li = i; sec = 1024; style = 1;
    } else if (i < NW_ + NWH) {
        S = W_hh; D = g_W2; li = i - NW_; sec = 1024; style = 1;
    } else if (i < NW_ + NWH + NEM) {
        S = emb; D = g_E2; li = i - NW_ - NWH; sec = 512; style = 0;
    } else if (i < NW_ + NWH + NEM + NWI) {
        S = W_ih; D = g_I2; li = i - NW_ - NWH - NEM; sec = 512; style = 1;
    } else return;
    float x = S[li];
    int m = (sec == 1024) ? (li >> 10) : (li >> 9);
    int k = li & (sec - 1);
    __nv_bfloat16 hi = __float2bfloat16(x);
    __nv_bfloat16 lo = __float2bfloat16(x - __bfloat162float(hi));
    __nv_bfloat16* r = D + (size_t)m * (3 * sec);
    if (style == 0) { r[k] = hi; r[k + sec] = hi; r[k + 2 * sec] = lo; }
    else            { r[k] = hi; r[k + sec] = lo; r[k + 2 * sec] = hi; }
}

// ---------------- pooling + prep fused (launch #2) -----------------------------
__global__ void pool_prep_kernel(const float* __restrict__ feat,
                                 const int* __restrict__ reports,
                                 const float* __restrict__ b_ih,
                                 const float* __restrict__ b_hh) {
    int bid = blockIdx.x, tid = threadIdx.x;
    if (bid < 256) {                  // pooling: 256 blocks cover 32*2048
        int i = bid * 256 + tid;
        const float* p = feat + (size_t)i * 49;
        float s = 0.f;
#pragma unroll
        for (int k = 0; k < 49; k++) s += p[k];
        g_pooled[i] = s * (1.0f / 49.0f);
    } else {                          // prep: 17 blocks cover 4096/4096/1
        int j = (bid - 256) * 256 + tid;
        if (j == 0) g_barcnt = 0u;
        if (j < G4) g_bsum[j] = b_ih[j] + b_hh[j];
        if (j < B_ * T_) g_idx[j] = ((j & (T_ - 1)) == 0) ? 1 : reports[j - 1];
    }
}

// ---------------- mma / ldmatrix helpers ----------------------------------------
__device__ __forceinline__ uint32_t smem_u32(const void* p) {
    uint32_t a;
    asm("{ .reg .u64 t; cvta.to.shared.u64 t, %1; cvt.u32.u64 %0, t; }"
        : "=r"(a) : "l"(p));
    return a;
}
__device__ __forceinline__ void mma_bf16(float* d, const uint32_t* a,
                                         const uint32_t* b) {
    asm volatile(
        "mma.sync.aligned.m16n8k16.row.col.f32.bf16.bf16.f32 "
        "{%0,%1,%2,%3}, {%4,%5,%6,%7}, {%8,%9}, {%0,%1,%2,%3};"
        : "+f"(d[0]), "+f"(d[1]), "+f"(d[2]), "+f"(d[3])
        : "r"(a[0]), "r"(a[1]), "r"(a[2]), "r"(a[3]), "r"(b[0]), "r"(b[1]));
}
__device__ __forceinline__ void ldsm_x4(uint32_t& r0, uint32_t& r1,
                                        uint32_t& r2, uint32_t& r3,
                                        uint32_t addr) {
    asm volatile("ldmatrix.sync.aligned.m8n8.x4.shared.b16 {%0,%1,%2,%3}, [%4];"
                 : "=r"(r0), "=r"(r1), "=r"(r2), "=r"(r3) : "r"(addr));
}
__device__ __forceinline__ float sigmoidf_(float x) {
    return 1.f / (1.f + expf(-x));
}

// ---------------- 128x128 bf16 mma GEMM (ldmatrix fragments) --------------------
// Smem rows: 32 bf16 (64B) = 4x16B segs; swizzle: seg' = seg ^ ((row&6)>>1).
template <int KTOT, bool GATHER>
__global__ void __launch_bounds__(256, 2)
mma_gemm_nt(const __nv_bfloat16* __restrict__ A2,
            const __nv_bfloat16* __restrict__ B2,
            const float* __restrict__ bias,
            float* __restrict__ C, int ncols,
            const int* __restrict__ ridx) {
    __shared__ uint32_t sA[2][128 * 16];   // 8KB per buf
    __shared__ uint32_t sB[2][128 * 16];

    const int NK = KTOT / 32;
    int tid = threadIdx.x;
    int lane = tid & 31, w = tid >> 5;
    int g = lane >> 2, tig = lane & 3;
    int wm = w >> 2, wn = w & 3;
    int laneq = lane >> 4;          // 16-group
    int laneh = (lane >> 3) & 1;    // 8-group within 16
    int lane15 = lane & 15, lane7 = lane & 7;

    int m0 = blockIdx.x * 128;
    int n0 = blockIdx.y * 128;

    uint32_t sA0 = smem_u32(sA), sB0 = smem_u32(sB);

    // loader mapping: row = tid>>1, half = tid&1 (2 uint4 per row per chunk)
    int lrow = tid >> 1;
    int lhalf = tid & 1;
    int ar = GATHER ? ridx[m0 + lrow] : (m0 + lrow);
    const uint4* pa = (const uint4*)(A2 + (size_t)ar * KTOT) + lhalf * 2;
    const uint4* pb = (const uint4*)(B2 + (size_t)(n0 + lrow) * KTOT) + lhalf * 2;
    int sw = lrow & 6;
    int st0 = (lrow << 4) + (((lhalf * 4 + 0) ^ sw) << 1);
    int st1 = (lrow << 4) + (((lhalf * 4 + 2) ^ sw) << 1);

    // ldmatrix address invariants
    uint32_t aterm[4], aswz[4];
#pragma unroll
    for (int mt = 0; mt < 4; mt++) {
        int rowA = wm * 64 + mt * 16 + lane15;
        aterm[mt] = (uint32_t)rowA * 64u;
        aswz[mt] = (uint32_t)((rowA & 6) >> 1);
    }
    uint32_t bterm[2], bswz[2];
#pragma unroll
    for (int ntp = 0; ntp < 2; ntp++) {
        int rowB = wn * 32 + (2 * ntp + laneq) * 8 + lane7;
        bterm[ntp] = (uint32_t)rowB * 64u;
        bswz[ntp] = (uint32_t)((rowB & 6) >> 1);
    }

    float acc[4][4][4];
#pragma unroll
    for (int i = 0; i < 4; i++)
#pragma unroll
        for (int j = 0; j < 4; j++)
#pragma unroll
            for (int q = 0; q < 4; q++) acc[i][j][q] = 0.f;

    uint4 ra0 = pa[0], ra1 = pa[1];
    uint4 rb0 = pb[0], rb1 = pb[1];

    for (int kc = 0; kc < NK; kc++) {
        int p = kc & 1;
        *(uint4*)&sA[p][st0] = ra0;
        *(uint4*)&sA[p][st1] = ra1;
        *(uint4*)&sB[p][st0] = rb0;
        *(uint4*)&sB[p][st1] = rb1;
        __syncthreads();

        if (kc + 1 < NK) {
            ra0 = pa[(kc + 1) * 4 + 0]; ra1 = pa[(kc + 1) * 4 + 1];
            rb0 = pb[(kc + 1) * 4 + 0]; rb1 = pb[(kc + 1) * 4 + 1];
        }

        uint32_t abase = sA0 + (uint32_t)p * 8192u;
        uint32_t bbase = sB0 + (uint32_t)p * 8192u;
#pragma unroll
        for (int ks = 0; ks < 2; ks++) {
            uint32_t bf[4][2];
            {
                uint32_t segb = (uint32_t)(2 * ks + laneh);
                ldsm_x4(bf[0][0], bf[0][1], bf[1][0], bf[1][1],
                        bbase + bterm[0] + (((segb ^ bswz[0])) << 4));
                ldsm_x4(bf[2][0], bf[2][1], bf[3][0], bf[3][1],
                        bbase + bterm[1] + (((segb ^ bswz[1])) << 4));
            }
            uint32_t sega = (uint32_t)(2 * ks + laneq);
#pragma unroll
            for (int mt = 0; mt < 4; mt++) {
                uint32_t af[4];
                ldsm_x4(af[0], af[1], af[2], af[3],
                        abase + aterm[mt] + (((sega ^ aswz[mt])) << 4));
#pragma unroll
                for (int nt = 0; nt < 4; nt++)
                    mma_bf16(acc[mt][nt], af, bf[nt]);
            }
        }
        __syncthreads();
    }

#pragma unroll
    for (int mt = 0; mt < 4; mt++) {
#pragma unroll
        for (int i2 = 0; i2 < 2; i2++) {
            int row = m0 + wm * 64 + mt * 16 + g + i2 * 8;
            float* crow = C + (size_t)row * ncols;
#pragma unroll
            for (int nt = 0; nt < 4; nt++) {
                int col = n0 + wn * 32 + nt * 8 + 2 * tig;
                float b0 = __ldg(&bias[col]);
                float b1 = __ldg(&bias[col + 1]);
                crow[col]     = acc[mt][nt][i2 * 2]     + b0;
                crow[col + 1] = acc[mt][nt][i2 * 2 + 1] + b1;
            }
        }
    }
}

// ---------------- persistent tensor-core LSTM (launch #4) -----------------------
// fc-init computed in prologue (block slice only). 256 threads, W slice in SMEM.
__global__ void __launch_bounds__(256, 1)
lstm_persistent(const float* __restrict__ fc_W, const float* __restrict__ fc_b) {
    extern __shared__ char smem[];
    uint32_t* sW = (uint32_t*)smem;                    // 96 slabs x 2048B = 192KB
    uint32_t* sA = (uint32_t*)(smem + 196608);         // 2 x 16KB
    float*  Csum = (float*)(smem + 196608);            // overlay (16.9KB)

    int tid = threadIdx.x;
    int lane = tid & 31, w = tid >> 5;
    int g = lane >> 2, tig = lane & 3;
    int wm = w >> 2, wk = w & 3;
    int u0 = blockIdx.x * 8;
    int laneq = lane >> 4;
    int laneh = (lane >> 3) & 1;
    int lane15 = lane & 15, lane7 = lane & 7;

    uint32_t sW0 = smem_u32(sW), sA0 = smem_u32(sA);

    // ---- one-time: stage W slice ----
    {
        int r = tid >> 3, e = tid & 7;
        int grow = ((r >> 3) << 10) + u0 + (r & 7);
        const uint4* wrow = (const uint4*)(g_W2 + (size_t)grow * KC);
        int sw = (r & 6) << 1;
#pragma unroll 4
        for (int j = 0; j < 48; j++) {
            int idx = e + j * 8;
            uint4 v = wrow[idx];
            int s = idx >> 2, q = (idx & 3) * 4;
            *(uint4*)&sW[s * 512 + r * 16 + (q ^ sw)] = v;
        }
    }

    // ---- fc prologue: this block's 16 init columns (8 h + 8 c) ----
    int cb = tid >> 3, cu = tid & 7;
    int uu = u0 + cu;
    float acch = fc_b[uu], accc = fc_b[H_ + uu];
    {
        const float4* pp  = (const float4*)(g_pooled + cb * F_);
        const float4* pwh = (const float4*)(fc_W + (size_t)uu * F_);
        const float4* pwc = (const float4*)(fc_W + (size_t)(H_ + uu) * F_);
#pragma unroll 4
        for (int k = 0; k < F_ / 4; k++) {
            float4 p = pp[k], a = pwh[k], b = pwc[k];
            acch += p.x * a.x + p.y * a.y + p.z * a.z + p.w * a.w;
            accc += p.x * b.x + p.y * b.y + p.z * b.z + p.w * b.w;
        }
    }
    float creg = accc;
    {
        __nv_bfloat16 hi = __float2bfloat16(acch);
        __nv_bfloat16 lo = __float2bfloat16(acch - __bfloat162float(hi));
        __nv_bfloat16* r = g_A0 + cb * KC;
        r[uu] = hi; r[uu + 1024] = hi; r[uu + 2048] = lo;
    }
    __threadfence();

    unsigned epoch = 0;
    volatile unsigned* vb = &g_barcnt;
#define GRIDBAR() do {                                              \
        __syncthreads();                                            \
        epoch++;                                                    \
        if (tid == 0) {                                             \
            atomicAdd(&g_barcnt, 1u);                               \
            while (*vb < epoch * (unsigned)NBLK) __nanosleep(64);   \
            __threadfence();                                        \
        }                                                           \
        __syncthreads();                                            \
    } while (0)

    GRIDBAR();

    int lr = tid >> 3, le = tid & 7;
    int lsw = (lr & 6) << 1;

    // ldmatrix invariants
    uint32_t aterm, aswz;
    {
        int rowA = wm * 16 + lane15;
        aterm = (uint32_t)rowA * 64u;
        aswz = (uint32_t)((rowA & 6) >> 1);
    }
    uint32_t wterm[2], wswz[2];
#pragma unroll
    for (int ntp = 0; ntp < 2; ntp++) {
        int rowW = (2 * ntp + laneq) * 8 + lane7;
        wterm[ntp] = (uint32_t)rowW * 64u;
        wswz[ntp] = (uint32_t)((rowW & 6) >> 1);
    }

    for (int t = 0; t < T_; t++) {
        const __nv_bfloat16* Abase =
            (t == 0) ? (g_A0 + lr * KC)
                     : (g_A2 + ((size_t)(lr * T_ + (t - 1))) * KC);
        const uint4* arow = (const uint4*)Abase;

        const float* xp = g_xproj + ((size_t)(cb * T_ + t)) * G4 + uu;
        float xp0 = xp[0], xp1 = xp[1024], xp2 = xp[2048], xp3 = xp[3072];

        float acc[4][4];
#pragma unroll
        for (int i = 0; i < 4; i++)
#pragma unroll
            for (int q = 0; q < 4; q++) acc[i][q] = 0.f;

#pragma unroll
        for (int j = 0; j < 4; j++) {
            int cu4 = le + j * 8;
            uint4 v = arow[cu4];
            int s = cu4 >> 2, q = (cu4 & 3) * 4;
            *(uint4*)&sA[s * 512 + lr * 16 + (q ^ lsw)] = v;
        }
        __syncthreads();

        for (int kc = 0; kc < 12; kc++) {
            int p = kc & 1;
            if (kc + 1 < 12) {
                int pb = p ^ 1;
#pragma unroll
                for (int j = 0; j < 4; j++) {
                    int cu4 = le + j * 8;
                    uint4 v = arow[(kc + 1) * 32 + cu4];
                    int s = cu4 >> 2, q = (cu4 & 3) * 4;
                    *(uint4*)&sA[pb * 4096 + s * 512 + lr * 16 + (q ^ lsw)] = v;
                }
            }
            uint32_t abase = sA0 + (uint32_t)p * 16384u;
#pragma unroll
            for (int jj = 0; jj < 4; jj++) {
                int j16 = jj * 4 + wk;
                int s = j16 >> 1, h = j16 & 1;
                uint32_t slabA = abase + (uint32_t)s * 2048u;
                uint32_t slabW = sW0 + (uint32_t)(kc * 8 + s) * 2048u;
                uint32_t af[4];
                ldsm_x4(af[0], af[1], af[2], af[3],
                        slabA + aterm + ((((uint32_t)(2 * h + laneq)) ^ aswz) << 4));
                uint32_t bf[4][2];
                uint32_t segw = (uint32_t)(2 * h + laneh);
                ldsm_x4(bf[0][0], bf[0][1], bf[1][0], bf[1][1],
                        slabW + wterm[0] + ((segw ^ wswz[0]) << 4));
                ldsm_x4(bf[2][0], bf[2][1], bf[3][0], bf[3][1],
                        slabW + wterm[1] + ((segw ^ wswz[1]) << 4));
#pragma unroll
                for (int nt = 0; nt < 4; nt++)
                    mma_bf16(acc[nt], af, bf[nt]);
            }
            __syncthreads();
        }

#pragma unroll
        for (int nt = 0; nt < 4; nt++) {
#pragma unroll
            for (int i2 = 0; i2 < 2; i2++) {
                int m = wm * 16 + g + i2 * 8;
                int n = nt * 8 + 2 * tig;
                Csum[(wk * 32 + m) * 33 + n]     = acc[nt][i2 * 2];
                Csum[(wk * 32 + m) * 33 + n + 1] = acc[nt][i2 * 2 + 1];
            }
        }
        __syncthreads();

        {
            float gate[4];
#pragma unroll
            for (int g4 = 0; g4 < 4; g4++) {
                int n = g4 * 8 + cu;
                gate[g4] = Csum[(0 * 32 + cb) * 33 + n] + Csum[(1 * 32 + cb) * 33 + n]
                         + Csum[(2 * 32 + cb) * 33 + n] + Csum[(3 * 32 + cb) * 33 + n];
            }
            gate[0] += xp0; gate[1] += xp1; gate[2] += xp2; gate[3] += xp3;
            float cn = sigmoidf_(gate[1]) * creg + sigmoidf_(gate[0]) * tanhf(gate[2]);
            float hn = sigmoidf_(gate[3]) * tanhf(cn);
            creg = cn;
            __nv_bfloat16 hi = __float2bfloat16(hn);
            __nv_bfloat16 lo = __float2bfloat16(hn - __bfloat162float(hi));
            __nv_bfloat16* r = g_A2 + ((size_t)(cb * T_ + t)) * KC;
            r[uu] = hi; r[uu + 1024] = hi; r[uu + 2048] = lo;
        }
        __threadfence();
        GRIDBAR();
    }
#undef GRIDBAR
}

// ---------------- launcher ---------------------------------------------------------
extern "C" void kernel_launch(void* const* d_in, const int* in_sizes, int n_in,
                              void* d_out, int out_size) {
    const float* features = (const float*)d_in[0];
    const int*   reports  = (const int*)d_in[1];
    const float* fc_W     = (const float*)d_in[2];
    const float* fc_b     = (const float*)d_in[3];
    const float* emb      = (const float*)d_in[4];
    const float* W_ih     = (const float*)d_in[5];
    const float* W_hh     = (const float*)d_in[6];
    const float* b_ih     = (const float*)d_in[7];
    const float* b_hh     = (const float*)d_in[8];
    const float* Wv       = (const float*)d_in[9];
    const float* bv       = (const float*)d_in[10];
    float* out = (float*)d_out;

    float *xproj_p, *bsum_p;
    __nv_bfloat16 *A2_p, *B2_p, *E2_p, *I2_p;
    int* idx_p;
    cudaGetSymbolAddress((void**)&xproj_p,  g_xproj);
    cudaGetSymbolAddress((void**)&bsum_p,   g_bsum);
    cudaGetSymbolAddress((void**)&idx_p,    g_idx);
    cudaGetSymbolAddress((void**)&A2_p,     g_A2);
    cudaGetSymbolAddress((void**)&B2_p,     g_B2);
    cudaGetSymbolAddress((void**)&E2_p,     g_E2);
    cudaGetSymbolAddress((void**)&I2_p,     g_I2);

    cudaFuncSetAttribute(lstm_persistent,
                         cudaFuncAttributeMaxDynamicSharedMemorySize, 229376);

    // #1: fused bf16 splits
    int convN = NW_ + NWH + NEM + NWI;
    conv_all_kernel<<<(convN + 255) / 256, 256>>>(Wv, W_hh, emb, W_ih);

    // #2: pooling + prep
    pool_prep_kernel<<<273, 256>>>(features, reports, b_ih, b_hh);

    // #3: xproj = emb[idx] @ W_ih^T + bsum
    mma_gemm_nt<KE, true><<<dim3((B_ * T_) / 128, G4 / 128), 256>>>(
        E2_p, I2_p, bsum_p, xproj_p, G4, idx_p);

    // #4: persistent tensor-core LSTM (fc-init in prologue)  <-- ncu captures this
    lstm_persistent<<<NBLK, 256, 229376>>>(fc_W, fc_b);

    // #5: output projection
    mma_gemm_nt<KC, false><<<dim3((B_ * T_) / 128, V_ / 128), 256>>>(
        A2_p, B2_p, bv, out, V_, nullptr);
}

// round 8
// speedup vs baseline: 1.4109x; 1.1162x over previous
#include <cuda_runtime.h>
#include <cuda_bf16.h>
#include <math.h>
#include <stdint.h>

#define B_  32
#define T_  128
#define V_  16000
#define E_  512
#define H_  1024
#define F_  2048
#define G4  4096   // 4*H
#define KC  3072   // 3*H (split-K for H-sized operands)
#define KE  1536   // 3*E (split-K for E-sized operands)
#define NBLK 128   // persistent LSTM blocks

// ---------------- scratch (device globals: no allocation allowed) ----------
__device__ float g_pooled[B_ * F_];
__device__ float g_bsum[G4];
__device__ int   g_idx[B_ * T_];
__device__ float g_xproj[(size_t)B_ * T_ * G4];        // 67 MB
__device__ __nv_bfloat16 g_A2[(size_t)B_ * T_ * KC];   // 25 MB  [hi|hi|lo]
__device__ __nv_bfloat16 g_B2[(size_t)V_ * KC];        // 98 MB  [hi|lo|hi]
__device__ __nv_bfloat16 g_W2[(size_t)G4 * KC];        // 25 MB  [hi|lo|hi]
__device__ __nv_bfloat16 g_E2[(size_t)V_ * KE];        // 49 MB  [hi|hi|lo]
__device__ __nv_bfloat16 g_I2[(size_t)G4 * KE];        // 12.6MB [hi|lo|hi]
__device__ __nv_bfloat16 g_A0[B_ * KC];                // h0 split
__device__ unsigned int  g_barcnt;

// ---------------- fused bf16 split conversions (launch #1) --------------------
#define NW_  (V_ * H_)
#define NWH  (G4 * H_)
#define NEM  (V_ * E_)
#define NWI  (G4 * E_)
__global__ void conv_all_kernel(const float* __restrict__ Wv,
                                const float* __restrict__ W_hh,
                                const float* __restrict__ emb,
                                const float* __restrict__ W_ih) {
    int i = blockIdx.x * blockDim.x + threadIdx.x;
    const float* S;
    __nv_bfloat16* D;
    int li, sec, style;
    if (i < NW_) {
        S = Wv; D = g_B2; li = i; sec = 1024; style = 1;
    } else if (i < NW_ + NWH) {
        S = W_hh; D = g_W2; li = i - NW_; sec = 1024; style = 1;
    } else if (i < NW_ + NWH + NEM) {
        S = emb; D = g_E2; li = i - NW_ - NWH; sec = 512; style = 0;
    } else if (i < NW_ + NWH + NEM + NWI) {
        S = W_ih; D = g_I2; li = i - NW_ - NWH - NEM; sec = 512; style = 1;
    } else return;
    float x = S[li];
    int m = (sec == 1024) ? (li >> 10) : (li >> 9);
    int k = li & (sec - 1);
    __nv_bfloat16 hi = __float2bfloat16(x);
    __nv_bfloat16 lo = __float2bfloat16(x - __bfloat162float(hi));
    __nv_bfloat16* r = D + (size_t)m * (3 * sec);
    if (style == 0) { r[k] = hi; r[k + sec] = hi; r[k + 2 * sec] = lo; }
    else            { r[k] = hi; r[k + sec] = lo; r[k + 2 * sec] = hi; }
}

// ---------------- pooling + prep fused (launch #2) -----------------------------
__global__ void pool_prep_kernel(const float* __restrict__ feat,
                                 const int* __restrict__ reports,
                                 const float* __restrict__ b_ih,
                                 const float* __restrict__ b_hh) {
    int bid = blockIdx.x, tid = threadIdx.x;
    if (bid < 256) {
        int i = bid * 256 + tid;
        const float* p = feat + (size_t)i * 49;
        float s = 0.f;
#pragma unroll
        for (int k = 0; k < 49; k++) s += p[k];
        g_pooled[i] = s * (1.0f / 49.0f);
    } else {
        int j = (bid - 256) * 256 + tid;
        if (j == 0) g_barcnt = 0u;
        if (j < G4) g_bsum[j] = b_ih[j] + b_hh[j];
        if (j < B_ * T_) g_idx[j] = ((j & (T_ - 1)) == 0) ? 1 : reports[j - 1];
    }
}

// ---------------- mma / ldmatrix helpers ----------------------------------------
__device__ __forceinline__ uint32_t smem_u32(const void* p) {
    uint32_t a;
    asm("{ .reg .u64 t; cvta.to.shared.u64 t, %1; cvt.u32.u64 %0, t; }"
        : "=r"(a) : "l"(p));
    return a;
}
__device__ __forceinline__ void mma_bf16(float* d, const uint32_t* a,
                                         const uint32_t* b) {
    asm volatile(
        "mma.sync.aligned.m16n8k16.row.col.f32.bf16.bf16.f32 "
        "{%0,%1,%2,%3}, {%4,%5,%6,%7}, {%8,%9}, {%0,%1,%2,%3};"
        : "+f"(d[0]), "+f"(d[1]), "+f"(d[2]), "+f"(d[3])
        : "r"(a[0]), "r"(a[1]), "r"(a[2]), "r"(a[3]), "r"(b[0]), "r"(b[1]));
}
__device__ __forceinline__ void ldsm_x4(uint32_t& r0, uint32_t& r1,
                                        uint32_t& r2, uint32_t& r3,
                                        uint32_t addr) {
    asm volatile("ldmatrix.sync.aligned.m8n8.x4.shared.b16 {%0,%1,%2,%3}, [%4];"
                 : "=r"(r0), "=r"(r1), "=r"(r2), "=r"(r3) : "r"(addr));
}
__device__ __forceinline__ float sigmoidf_(float x) {
    return 1.f / (1.f + expf(-x));
}

// ---------------- 128x128 bf16 mma GEMM (ldmatrix fragments) --------------------
template <int KTOT, bool GATHER>
__global__ void __launch_bounds__(256, 2)
mma_gemm_nt(const __nv_bfloat16* __restrict__ A2,
            const __nv_bfloat16* __restrict__ B2,
            const float* __restrict__ bias,
            float* __restrict__ C, int ncols,
            const int* __restrict__ ridx) {
    __shared__ uint32_t sA[2][128 * 16];
    __shared__ uint32_t sB[2][128 * 16];

    const int NK = KTOT / 32;
    int tid = threadIdx.x;
    int lane = tid & 31, w = tid >> 5;
    int g = lane >> 2, tig = lane & 3;
    int wm = w >> 2, wn = w & 3;
    int laneq = lane >> 4;
    int laneh = (lane >> 3) & 1;
    int lane15 = lane & 15, lane7 = lane & 7;

    int m0 = blockIdx.x * 128;
    int n0 = blockIdx.y * 128;

    uint32_t sA0 = smem_u32(sA), sB0 = smem_u32(sB);

    int lrow = tid >> 1;
    int lhalf = tid & 1;
    int ar = GATHER ? ridx[m0 + lrow] : (m0 + lrow);
    const uint4* pa = (const uint4*)(A2 + (size_t)ar * KTOT) + lhalf * 2;
    const uint4* pb = (const uint4*)(B2 + (size_t)(n0 + lrow) * KTOT) + lhalf * 2;
    int sw = lrow & 6;
    int st0 = (lrow << 4) + (((lhalf * 4 + 0) ^ sw) << 1);
    int st1 = (lrow << 4) + (((lhalf * 4 + 2) ^ sw) << 1);

    uint32_t aterm[4], aswz[4];
#pragma unroll
    for (int mt = 0; mt < 4; mt++) {
        int rowA = wm * 64 + mt * 16 + lane15;
        aterm[mt] = (uint32_t)rowA * 64u;
        aswz[mt] = (uint32_t)((rowA & 6) >> 1);
    }
    uint32_t bterm[2], bswz[2];
#pragma unroll
    for (int ntp = 0; ntp < 2; ntp++) {
        int rowB = wn * 32 + (2 * ntp + laneq) * 8 + lane7;
        bterm[ntp] = (uint32_t)rowB * 64u;
        bswz[ntp] = (uint32_t)((rowB & 6) >> 1);
    }

    float acc[4][4][4];
#pragma unroll
    for (int i = 0; i < 4; i++)
#pragma unroll
        for (int j = 0; j < 4; j++)
#pragma unroll
            for (int q = 0; q < 4; q++) acc[i][j][q] = 0.f;

    uint4 ra0 = pa[0], ra1 = pa[1];
    uint4 rb0 = pb[0], rb1 = pb[1];

    for (int kc = 0; kc < NK; kc++) {
        int p = kc & 1;
        *(uint4*)&sA[p][st0] = ra0;
        *(uint4*)&sA[p][st1] = ra1;
        *(uint4*)&sB[p][st0] = rb0;
        *(uint4*)&sB[p][st1] = rb1;
        __syncthreads();

        if (kc + 1 < NK) {
            ra0 = pa[(kc + 1) * 4 + 0]; ra1 = pa[(kc + 1) * 4 + 1];
            rb0 = pb[(kc + 1) * 4 + 0]; rb1 = pb[(kc + 1) * 4 + 1];
        }

        uint32_t abase = sA0 + (uint32_t)p * 8192u;
        uint32_t bbase = sB0 + (uint32_t)p * 8192u;
#pragma unroll
        for (int ks = 0; ks < 2; ks++) {
            uint32_t bf[4][2];
            {
                uint32_t segb = (uint32_t)(2 * ks + laneh);
                ldsm_x4(bf[0][0], bf[0][1], bf[1][0], bf[1][1],
                        bbase + bterm[0] + (((segb ^ bswz[0])) << 4));
                ldsm_x4(bf[2][0], bf[2][1], bf[3][0], bf[3][1],
                        bbase + bterm[1] + (((segb ^ bswz[1])) << 4));
            }
            uint32_t sega = (uint32_t)(2 * ks + laneq);
#pragma unroll
            for (int mt = 0; mt < 4; mt++) {
                uint32_t af[4];
                ldsm_x4(af[0], af[1], af[2], af[3],
                        abase + aterm[mt] + (((sega ^ aswz[mt])) << 4));
#pragma unroll
                for (int nt = 0; nt < 4; nt++)
                    mma_bf16(acc[mt][nt], af, bf[nt]);
            }
        }
        __syncthreads();
    }

#pragma unroll
    for (int mt = 0; mt < 4; mt++) {
#pragma unroll
        for (int i2 = 0; i2 < 2; i2++) {
            int row = m0 + wm * 64 + mt * 16 + g + i2 * 8;
            float* crow = C + (size_t)row * ncols;
#pragma unroll
            for (int nt = 0; nt < 4; nt++) {
                int col = n0 + wn * 32 + nt * 8 + 2 * tig;
                float b0 = __ldg(&bias[col]);
                float b1 = __ldg(&bias[col + 1]);
                crow[col]     = acc[mt][nt][i2 * 2]     + b0;
                crow[col + 1] = acc[mt][nt][i2 * 2 + 1] + b1;
            }
        }
    }
}

// ---------------- persistent tensor-core LSTM (launch #4) -----------------------
// R8: 1 syncthreads per chunk, software-pipelined ldsm/mma fragments,
// xproj prefetch hoisted across the grid barrier.
__global__ void __launch_bounds__(256, 1)
lstm_persistent(const float* __restrict__ fc_W, const float* __restrict__ fc_b) {
    extern __shared__ char smem[];
    uint32_t* sW = (uint32_t*)smem;                    // 96 slabs x 2048B = 192KB
    uint32_t* sA = (uint32_t*)(smem + 196608);         // 2 x 16KB
    float*  Csum = (float*)(smem + 196608);            // overlay (16.9KB)

    int tid = threadIdx.x;
    int lane = tid & 31, w = tid >> 5;
    int g = lane >> 2, tig = lane & 3;
    int wm = w >> 2, wk = w & 3;
    int u0 = blockIdx.x * 8;
    int laneq = lane >> 4;
    int laneh = (lane >> 3) & 1;
    int lane15 = lane & 15, lane7 = lane & 7;

    uint32_t sW0 = smem_u32(sW), sA0 = smem_u32(sA);

    // ---- one-time: stage W slice ----
    {
        int r = tid >> 3, e = tid & 7;
        int grow = ((r >> 3) << 10) + u0 + (r & 7);
        const uint4* wrow = (const uint4*)(g_W2 + (size_t)grow * KC);
        int sw = (r & 6) << 1;
#pragma unroll 4
        for (int j = 0; j < 48; j++) {
            int idx = e + j * 8;
            uint4 v = wrow[idx];
            int s = idx >> 2, q = (idx & 3) * 4;
            *(uint4*)&sW[s * 512 + r * 16 + (q ^ sw)] = v;
        }
    }

    // ---- fc prologue: this block's 16 init columns (8 h + 8 c) ----
    int cb = tid >> 3, cu = tid & 7;
    int uu = u0 + cu;
    float acch = fc_b[uu], accc = fc_b[H_ + uu];
    {
        const float4* pp  = (const float4*)(g_pooled + cb * F_);
        const float4* pwh = (const float4*)(fc_W + (size_t)uu * F_);
        const float4* pwc = (const float4*)(fc_W + (size_t)(H_ + uu) * F_);
#pragma unroll 4
        for (int k = 0; k < F_ / 4; k++) {
            float4 p = pp[k], a = pwh[k], b = pwc[k];
            acch += p.x * a.x + p.y * a.y + p.z * a.z + p.w * a.w;
            accc += p.x * b.x + p.y * b.y + p.z * b.z + p.w * b.w;
        }
    }
    float creg = accc;
    {
        __nv_bfloat16 hi = __float2bfloat16(acch);
        __nv_bfloat16 lo = __float2bfloat16(acch - __bfloat162float(hi));
        __nv_bfloat16* r = g_A0 + cb * KC;
        r[uu] = hi; r[uu + 1024] = hi; r[uu + 2048] = lo;
    }
    __threadfence();

    unsigned epoch = 0;
    volatile unsigned* vb = &g_barcnt;
#define GRIDBAR() do {                                              \
        __syncthreads();                                            \
        epoch++;                                                    \
        if (tid == 0) {                                             \
            atomicAdd(&g_barcnt, 1u);                               \
            while (*vb < epoch * (unsigned)NBLK) __nanosleep(64);   \
            __threadfence();                                        \
        }                                                           \
        __syncthreads();                                            \
    } while (0)

    GRIDBAR();

    int lr = tid >> 3, le = tid & 7;
    int lsw = (lr & 6) << 1;

    // ldmatrix address invariants
    uint32_t aterm, aswz;
    {
        int rowA = wm * 16 + lane15;
        aterm = (uint32_t)rowA * 64u;
        aswz = (uint32_t)((rowA & 6) >> 1);
    }
    uint32_t wterm[2], wswz[2];
#pragma unroll
    for (int ntp = 0; ntp < 2; ntp++) {
        int rowW = (2 * ntp + laneq) * 8 + lane7;
        wterm[ntp] = (uint32_t)rowW * 64u;
        wswz[ntp] = (uint32_t)((rowW & 6) >> 1);
    }

// fragment load for (kc, jj) into register buffer `buf`
#define LOADFRAG(buf, kc_, jj_, abase_) do {                                  \
        int j16_ = (jj_) * 4 + wk;                                            \
        int s_ = j16_ >> 1, h_ = j16_ & 1;                                    \
        uint32_t slabA_ = (abase_) + (uint32_t)s_ * 2048u;                    \
        uint32_t slabW_ = sW0 + (uint32_t)((kc_) * 8 + s_) * 2048u;           \
        ldsm_x4(af[buf][0], af[buf][1], af[buf][2], af[buf][3],               \
                slabA_ + aterm + ((((uint32_t)(2 * h_ + laneq)) ^ aswz) << 4));\
        uint32_t segw_ = (uint32_t)(2 * h_ + laneh);                          \
        ldsm_x4(bf[buf][0][0], bf[buf][0][1], bf[buf][1][0], bf[buf][1][1],   \
                slabW_ + wterm[0] + ((segw_ ^ wswz[0]) << 4));                \
        ldsm_x4(bf[buf][2][0], bf[buf][2][1], bf[buf][3][0], bf[buf][3][1],   \
                slabW_ + wterm[1] + ((segw_ ^ wswz[1]) << 4));                \
    } while (0)

    // xproj prefetch for t = 0
    float xp0, xp1, xp2, xp3;
    {
        const float* xp = g_xproj + ((size_t)(cb * T_ + 0)) * G4 + uu;
        xp0 = xp[0]; xp1 = xp[1024]; xp2 = xp[2048]; xp3 = xp[3072];
    }

    for (int t = 0; t < T_; t++) {
        const __nv_bfloat16* Abase =
            (t == 0) ? (g_A0 + lr * KC)
                     : (g_A2 + ((size_t)(lr * T_ + (t - 1))) * KC);
        const uint4* arow = (const uint4*)Abase;

        float acc[4][4];
#pragma unroll
        for (int i = 0; i < 4; i++)
#pragma unroll
            for (int q = 0; q < 4; q++) acc[i][q] = 0.f;

        uint4 va[4];
        // load + store chunk 0
#pragma unroll
        for (int j = 0; j < 4; j++) va[j] = arow[le + j * 8];
#pragma unroll
        for (int j = 0; j < 4; j++) {
            int cu4 = le + j * 8;
            int s = cu4 >> 2, q = (cu4 & 3) * 4;
            *(uint4*)&sA[s * 512 + lr * 16 + (q ^ lsw)] = va[j];
        }
        // load chunk 1
#pragma unroll
        for (int j = 0; j < 4; j++) va[j] = arow[32 + le + j * 8];
        __syncthreads();

        for (int kc = 0; kc < 12; kc++) {
            int p = kc & 1;
            // store chunk kc+1 into buffer p^1 (its readers synced out last iter)
            if (kc < 11) {
                uint32_t boff = (uint32_t)(p ^ 1) * 4096u;
#pragma unroll
                for (int j = 0; j < 4; j++) {
                    int cu4 = le + j * 8;
                    int s = cu4 >> 2, q = (cu4 & 3) * 4;
                    *(uint4*)&sA[boff + s * 512 + lr * 16 + (q ^ lsw)] = va[j];
                }
                if (kc < 10) {
#pragma unroll
                    for (int j = 0; j < 4; j++)
                        va[j] = arow[(kc + 2) * 32 + le + j * 8];
                }
            }
            uint32_t abase = sA0 + (uint32_t)p * 16384u;
            // software-pipelined fragment loads
            uint32_t af[2][4], bf[2][4][2];
            LOADFRAG(0, kc, 0, abase);
#pragma unroll
            for (int jj = 0; jj < 4; jj++) {
                if (jj < 3) LOADFRAG((jj + 1) & 1, kc, jj + 1, abase);
                int cur = jj & 1;
#pragma unroll
                for (int nt = 0; nt < 4; nt++)
                    mma_bf16(acc[nt], af[cur], bf[cur][nt]);
            }
            __syncthreads();   // single barrier: protects p reads + p^1 writes
        }

#pragma unroll
        for (int nt = 0; nt < 4; nt++) {
#pragma unroll
            for (int i2 = 0; i2 < 2; i2++) {
                int m = wm * 16 + g + i2 * 8;
                int n = nt * 8 + 2 * tig;
                Csum[(wk * 32 + m) * 33 + n]     = acc[nt][i2 * 2];
                Csum[(wk * 32 + m) * 33 + n + 1] = acc[nt][i2 * 2 + 1];
            }
        }
        __syncthreads();

        {
            float gate[4];
#pragma unroll
            for (int g4 = 0; g4 < 4; g4++) {
                int n = g4 * 8 + cu;
                gate[g4] = Csum[(0 * 32 + cb) * 33 + n] + Csum[(1 * 32 + cb) * 33 + n]
                         + Csum[(2 * 32 + cb) * 33 + n] + Csum[(3 * 32 + cb) * 33 + n];
            }
            gate[0] += xp0; gate[1] += xp1; gate[2] += xp2; gate[3] += xp3;
            float cn = sigmoidf_(gate[1]) * creg + sigmoidf_(gate[0]) * tanhf(gate[2]);
            float hn = sigmoidf_(gate[3]) * tanhf(cn);
            creg = cn;
            __nv_bfloat16 hi = __float2bfloat16(hn);
            __nv_bfloat16 lo = __float2bfloat16(hn - __bfloat162float(hi));
            __nv_bfloat16* r = g_A2 + ((size_t)(cb * T_ + t)) * KC;
            r[uu] = hi; r[uu + 1024] = hi; r[uu + 2048] = lo;
        }
        // prefetch xproj for t+1 BEFORE the barrier (precomputed, always valid)
        if (t + 1 < T_) {
            const float* xp = g_xproj + ((size_t)(cb * T_ + t + 1)) * G4 + uu;
            xp0 = xp[0]; xp1 = xp[1024]; xp2 = xp[2048]; xp3 = xp[3072];
        }
        __threadfence();
        GRIDBAR();
    }
#undef GRIDBAR
#undef LOADFRAG
}

// ---------------- launcher ---------------------------------------------------------
extern "C" void kernel_launch(void* const* d_in, const int* in_sizes, int n_in,
                              void* d_out, int out_size) {
    const float* features = (const float*)d_in[0];
    const int*   reports  = (const int*)d_in[1];
    const float* fc_W     = (const float*)d_in[2];
    const float* fc_b     = (const float*)d_in[3];
    const float* emb      = (const float*)d_in[4];
    const float* W_ih     = (const float*)d_in[5];
    const float* W_hh     = (const float*)d_in[6];
    const float* b_ih     = (const float*)d_in[7];
    const float* b_hh     = (const float*)d_in[8];
    const float* Wv       = (const float*)d_in[9];
    const float* bv       = (const float*)d_in[10];
    float* out = (float*)d_out;

    float *xproj_p, *bsum_p;
    __nv_bfloat16 *A2_p, *B2_p, *E2_p, *I2_p;
    int* idx_p;
    cudaGetSymbolAddress((void**)&xproj_p,  g_xproj);
    cudaGetSymbolAddress((void**)&bsum_p,   g_bsum);
    cudaGetSymbolAddress((void**)&idx_p,    g_idx);
    cudaGetSymbolAddress((void**)&A2_p,     g_A2);
    cudaGetSymbolAddress((void**)&B2_p,     g_B2);
    cudaGetSymbolAddress((void**)&E2_p,     g_E2);
    cudaGetSymbolAddress((void**)&I2_p,     g_I2);

    cudaFuncSetAttribute(lstm_persistent,
                         cudaFuncAttributeMaxDynamicSharedMemorySize, 229376);

    // #1: fused bf16 splits
    int convN = NW_ + NWH + NEM + NWI;
    conv_all_kernel<<<(convN + 255) / 256, 256>>>(Wv, W_hh, emb, W_ih);

    // #2: pooling + prep
    pool_prep_kernel<<<273, 256>>>(features, reports, b_ih, b_hh);

    // #3: xproj = emb[idx] @ W_ih^T + bsum
    mma_gemm_nt<KE, true><<<dim3((B_ * T_) / 128, G4 / 128), 256>>>(
        E2_p, I2_p, bsum_p, xproj_p, G4, idx_p);

    // #4: persistent tensor-core LSTM (fc-init in prologue)
    lstm_persistent<<<NBLK, 256, 229376>>>(fc_W, fc_b);

    // #5: output projection
    mma_gemm_nt<KC, false><<<dim3((B_ * T_) / 128, V_ / 128), 256>>>(
        A2_p, B2_p, bv, out, V_, nullptr);
}

// round 9
// speedup vs baseline: 1.4798x; 1.0488x over previous
#include <cuda_runtime.h>
#include <cuda_bf16.h>
#include <math.h>
#include <stdint.h>

#define B_  32
#define T_  128
#define V_  16000
#define E_  512
#define H_  1024
#define F_  2048
#define G4  4096   // 4*H
#define KC  3072   // 3*H contraction length (B-side [hi|lo|hi])
#define KA  2048   // A-side storage [hi|lo]
#define KE  1536   // 3*E (xproj, both sides stored full)
#define NBLK 128   // persistent LSTM blocks

// ---------------- scratch (device globals: no allocation allowed) ----------
__device__ float g_pooled[B_ * F_];
__device__ float g_bsum[G4];
__device__ int   g_idx[B_ * T_];
__device__ float g_xproj[(size_t)B_ * T_ * G4];        // 67 MB
__device__ __nv_bfloat16 g_A2[(size_t)B_ * T_ * KA];   // 16.8 MB [hi|lo]
__device__ __nv_bfloat16 g_B2[(size_t)V_ * KC];        // 98 MB  [hi|lo|hi]
__device__ __nv_bfloat16 g_W2[(size_t)G4 * KC];        // 25 MB  [hi|lo|hi]
__device__ __nv_bfloat16 g_E2[(size_t)V_ * KE];        // 49 MB  [hi|hi|lo]
__device__ __nv_bfloat16 g_I2[(size_t)G4 * KE];        // 12.6MB [hi|lo|hi]
__device__ __nv_bfloat16 g_A0[B_ * KA];                // h0 split [hi|lo]
__device__ unsigned int  g_barcnt;

// ---------------- fused bf16 split conversions (launch #1) --------------------
#define NW_  (V_ * H_)
#define NWH  (G4 * H_)
#define NEM  (V_ * E_)
#define NWI  (G4 * E_)
__global__ void conv_all_kernel(const float* __restrict__ Wv,
                                const float* __restrict__ W_hh,
                                const float* __restrict__ emb,
                                const float* __restrict__ W_ih) {
    int i = blockIdx.x * blockDim.x + threadIdx.x;
    const float* S;
    __nv_bfloat16* D;
    int li, sec, style;
    if (i < NW_) {
        S = Wv; D = g_B2; li = i; sec = 1024; style = 1;
    } else if (i < NW_ + NWH) {
        S = W_hh; D = g_W2; li = i - NW_; sec = 1024; style = 1;
    } else if (i < NW_ + NWH + NEM) {
        S = emb; D = g_E2; li = i - NW_ - NWH; sec = 512; style = 0;
    } else if (i < NW_ + NWH + NEM + NWI) {
        S = W_ih; D = g_I2; li = i - NW_ - NWH - NEM; sec = 512; style = 1;
    } else return;
    float x = S[li];
    int m = (sec == 1024) ? (li >> 10) : (li >> 9);
    int k = li & (sec - 1);
    __nv_bfloat16 hi = __float2bfloat16(x);
    __nv_bfloat16 lo = __float2bfloat16(x - __bfloat162float(hi));
    __nv_bfloat16* r = D + (size_t)m * (3 * sec);
    if (style == 0) { r[k] = hi; r[k + sec] = hi; r[k + 2 * sec] = lo; }
    else            { r[k] = hi; r[k + sec] = lo; r[k + 2 * sec] = hi; }
}

// ---------------- pooling + prep fused (launch #2) -----------------------------
__global__ void pool_prep_kernel(const float* __restrict__ feat,
                                 const int* __restrict__ reports,
                                 const float* __restrict__ b_ih,
                                 const float* __restrict__ b_hh) {
    int bid = blockIdx.x, tid = threadIdx.x;
    if (bid < 256) {
        int i = bid * 256 + tid;
        const float* p = feat + (size_t)i * 49;
        float s = 0.f;
#pragma unroll
        for (int k = 0; k < 49; k++) s += p[k];
        g_pooled[i] = s * (1.0f / 49.0f);
    } else {
        int j = (bid - 256) * 256 + tid;
        if (j == 0) g_barcnt = 0u;
        if (j < G4) g_bsum[j] = b_ih[j] + b_hh[j];
        if (j < B_ * T_) g_idx[j] = ((j & (T_ - 1)) == 0) ? 1 : reports[j - 1];
    }
}

// ---------------- mma / ldmatrix helpers ----------------------------------------
__device__ __forceinline__ uint32_t smem_u32(const void* p) {
    uint32_t a;
    asm("{ .reg .u64 t; cvta.to.shared.u64 t, %1; cvt.u32.u64 %0, t; }"
        : "=r"(a) : "l"(p));
    return a;
}
__device__ __forceinline__ void mma_bf16(float* d, const uint32_t* a,
                                         const uint32_t* b) {
    asm volatile(
        "mma.sync.aligned.m16n8k16.row.col.f32.bf16.bf16.f32 "
        "{%0,%1,%2,%3}, {%4,%5,%6,%7}, {%8,%9}, {%0,%1,%2,%3};"
        : "+f"(d[0]), "+f"(d[1]), "+f"(d[2]), "+f"(d[3])
        : "r"(a[0]), "r"(a[1]), "r"(a[2]), "r"(a[3]), "r"(b[0]), "r"(b[1]));
}
__device__ __forceinline__ void ldsm_x4(uint32_t& r0, uint32_t& r1,
                                        uint32_t& r2, uint32_t& r3,
                                        uint32_t addr) {
    asm volatile("ldmatrix.sync.aligned.m8n8.x4.shared.b16 {%0,%1,%2,%3}, [%4];"
                 : "=r"(r0), "=r"(r1), "=r"(r2), "=r"(r3) : "r"(addr));
}
__device__ __forceinline__ float sigmoidf_(float x) {
    return 1.f / (1.f + expf(-x));
}

// ---------------- 128x128 bf16 mma GEMM (ldmatrix fragments) --------------------
// KTOT = contraction length (B row length). AK = A row storage length.
// If AK < KTOT, chunks kc >= TH re-read A columns (kc-TH)*32 (A-hi reuse).
template <int KTOT, int AK, bool GATHER>
__global__ void __launch_bounds__(256, 2)
mma_gemm_nt(const __nv_bfloat16* __restrict__ A2,
            const __nv_bfloat16* __restrict__ B2,
            const float* __restrict__ bias,
            float* __restrict__ C, int ncols,
            const int* __restrict__ ridx) {
    __shared__ uint32_t sA[2][128 * 16];
    __shared__ uint32_t sB[2][128 * 16];

    const int NK = KTOT / 32;
    const int TH = (KTOT - AK) / 32;   // 0 when AK==KTOT
    int tid = threadIdx.x;
    int lane = tid & 31, w = tid >> 5;
    int g = lane >> 2, tig = lane & 3;
    int wm = w >> 2, wn = w & 3;
    int laneq = lane >> 4;
    int laneh = (lane >> 3) & 1;
    int lane15 = lane & 15, lane7 = lane & 7;

    int m0 = blockIdx.x * 128;
    int n0 = blockIdx.y * 128;

    uint32_t sA0 = smem_u32(sA), sB0 = smem_u32(sB);

    int lrow = tid >> 1;
    int lhalf = tid & 1;
    int ar = GATHER ? ridx[m0 + lrow] : (m0 + lrow);
    const uint4* pa = (const uint4*)(A2 + (size_t)ar * AK) + lhalf * 2;
    const uint4* pb = (const uint4*)(B2 + (size_t)(n0 + lrow) * KTOT) + lhalf * 2;
    int sw = lrow & 6;
    int st0 = (lrow << 4) + (((lhalf * 4 + 0) ^ sw) << 1);
    int st1 = (lrow << 4) + (((lhalf * 4 + 2) ^ sw) << 1);

    uint32_t aterm[4], aswz[4];
#pragma unroll
    for (int mt = 0; mt < 4; mt++) {
        int rowA = wm * 64 + mt * 16 + lane15;
        aterm[mt] = (uint32_t)rowA * 64u;
        aswz[mt] = (uint32_t)((rowA & 6) >> 1);
    }
    uint32_t bterm[2], bswz[2];
#pragma unroll
    for (int ntp = 0; ntp < 2; ntp++) {
        int rowB = wn * 32 + (2 * ntp + laneq) * 8 + lane7;
        bterm[ntp] = (uint32_t)rowB * 64u;
        bswz[ntp] = (uint32_t)((rowB & 6) >> 1);
    }

    float acc[4][4][4];
#pragma unroll
    for (int i = 0; i < 4; i++)
#pragma unroll
        for (int j = 0; j < 4; j++)
#pragma unroll
            for (int q = 0; q < 4; q++) acc[i][j][q] = 0.f;

    uint4 ra0 = pa[0], ra1 = pa[1];
    uint4 rb0 = pb[0], rb1 = pb[1];

    for (int kc = 0; kc < NK; kc++) {
        int p = kc & 1;
        *(uint4*)&sA[p][st0] = ra0;
        *(uint4*)&sA[p][st1] = ra1;
        *(uint4*)&sB[p][st0] = rb0;
        *(uint4*)&sB[p][st1] = rb1;
        __syncthreads();

        if (kc + 1 < NK) {
            int kn = kc + 1;
            int akc = (TH == 0) ? kn : ((kn < TH) ? kn : kn - TH);
            ra0 = pa[akc * 4 + 0]; ra1 = pa[akc * 4 + 1];
            rb0 = pb[kn * 4 + 0];  rb1 = pb[kn * 4 + 1];
        }

        uint32_t abase = sA0 + (uint32_t)p * 8192u;
        uint32_t bbase = sB0 + (uint32_t)p * 8192u;
#pragma unroll
        for (int ks = 0; ks < 2; ks++) {
            uint32_t bf[4][2];
            {
                uint32_t segb = (uint32_t)(2 * ks + laneh);
                ldsm_x4(bf[0][0], bf[0][1], bf[1][0], bf[1][1],
                        bbase + bterm[0] + (((segb ^ bswz[0])) << 4));
                ldsm_x4(bf[2][0], bf[2][1], bf[3][0], bf[3][1],
                        bbase + bterm[1] + (((segb ^ bswz[1])) << 4));
            }
            uint32_t sega = (uint32_t)(2 * ks + laneq);
#pragma unroll
            for (int mt = 0; mt < 4; mt++) {
                uint32_t af[4];
                ldsm_x4(af[0], af[1], af[2], af[3],
                        abase + aterm[mt] + (((sega ^ aswz[mt])) << 4));
#pragma unroll
                for (int nt = 0; nt < 4; nt++)
                    mma_bf16(acc[mt][nt], af, bf[nt]);
            }
        }
        __syncthreads();
    }

#pragma unroll
    for (int mt = 0; mt < 4; mt++) {
#pragma unroll
        for (int i2 = 0; i2 < 2; i2++) {
            int row = m0 + wm * 64 + mt * 16 + g + i2 * 8;
            float* crow = C + (size_t)row * ncols;
#pragma unroll
            for (int nt = 0; nt < 4; nt++) {
                int col = n0 + wn * 32 + nt * 8 + 2 * tig;
                float b0 = __ldg(&bias[col]);
                float b1 = __ldg(&bias[col + 1]);
                crow[col]     = acc[mt][nt][i2 * 2]     + b0;
                crow[col + 1] = acc[mt][nt][i2 * 2 + 1] + b1;
            }
        }
    }
}

// ---------------- persistent tensor-core LSTM (launch #4) -----------------------
// A stored [hi|lo] (2048): 8 chunks of 256. Per A-k16 a (0..127), mma with
// W slab (a+64); additionally, if a<64, mma with W slab a.
__global__ void __launch_bounds__(256, 1)
lstm_persistent(const float* __restrict__ fc_W, const float* __restrict__ fc_b) {
    extern __shared__ char smem[];
    uint32_t* sW = (uint32_t*)smem;                    // 96 slabs x 2048B = 192KB
    uint32_t* sA = (uint32_t*)(smem + 196608);         // 2 x 16KB
    float*  Csum = (float*)(smem + 196608);            // overlay (16.9KB)

    int tid = threadIdx.x;
    int lane = tid & 31, w = tid >> 5;
    int g = lane >> 2, tig = lane & 3;
    int wm = w >> 2, wk = w & 3;
    int u0 = blockIdx.x * 8;
    int laneq = lane >> 4;
    int laneh = (lane >> 3) & 1;
    int lane15 = lane & 15, lane7 = lane & 7;

    uint32_t sW0 = smem_u32(sW), sA0 = smem_u32(sA);

    // ---- one-time: stage W slice [32 rows x 3072] ----
    {
        int r = tid >> 3, e = tid & 7;
        int grow = ((r >> 3) << 10) + u0 + (r & 7);
        const uint4* wrow = (const uint4*)(g_W2 + (size_t)grow * KC);
        int sw = (r & 6) << 1;
#pragma unroll 4
        for (int j = 0; j < 48; j++) {
            int idx = e + j * 8;
            uint4 v = wrow[idx];
            int s = idx >> 2, q = (idx & 3) * 4;
            *(uint4*)&sW[s * 512 + r * 16 + (q ^ sw)] = v;
        }
    }

    // ---- fc prologue: this block's 16 init columns (8 h + 8 c) ----
    int cb = tid >> 3, cu = tid & 7;
    int uu = u0 + cu;
    float acch = fc_b[uu], accc = fc_b[H_ + uu];
    {
        const float4* pp  = (const float4*)(g_pooled + cb * F_);
        const float4* pwh = (const float4*)(fc_W + (size_t)uu * F_);
        const float4* pwc = (const float4*)(fc_W + (size_t)(H_ + uu) * F_);
#pragma unroll 4
        for (int k = 0; k < F_ / 4; k++) {
            float4 p = pp[k], a = pwh[k], b = pwc[k];
            acch += p.x * a.x + p.y * a.y + p.z * a.z + p.w * a.w;
            accc += p.x * b.x + p.y * b.y + p.z * b.z + p.w * b.w;
        }
    }
    float creg = accc;
    {
        __nv_bfloat16 hi = __float2bfloat16(acch);
        __nv_bfloat16 lo = __float2bfloat16(acch - __bfloat162float(hi));
        __nv_bfloat16* r = g_A0 + cb * KA;
        r[uu] = hi; r[uu + 1024] = lo;
    }
    __threadfence();

    unsigned epoch = 0;
    volatile unsigned* vb = &g_barcnt;
#define GRIDBAR() do {                                              \
        __syncthreads();                                            \
        epoch++;                                                    \
        if (tid == 0) {                                             \
            atomicAdd(&g_barcnt, 1u);                               \
            while (*vb < epoch * (unsigned)NBLK) {}                 \
            __threadfence();                                        \
        }                                                           \
        __syncthreads();                                            \
    } while (0)

    GRIDBAR();

    int lr = tid >> 3, le = tid & 7;
    int lsw = (lr & 6) << 1;

    // ldmatrix address invariants
    uint32_t aterm, aswz;
    {
        int rowA = wm * 16 + lane15;
        aterm = (uint32_t)rowA * 64u;
        aswz = (uint32_t)((rowA & 6) >> 1);
    }
    uint32_t wterm[2], wswz[2];
#pragma unroll
    for (int ntp = 0; ntp < 2; ntp++) {
        int rowW = (2 * ntp + laneq) * 8 + lane7;
        wterm[ntp] = (uint32_t)rowW * 64u;
        wswz[ntp] = (uint32_t)((rowW & 6) >> 1);
    }

// pipelined fragment load: A frag + W frag for slab (a16+64)
#define LOADFRAG(buf, kc_, jj_, abase_) do {                                  \
        int j16_ = (jj_) * 4 + wk;                                            \
        int s_ = j16_ >> 1, h_ = j16_ & 1;                                    \
        uint32_t slabA_ = (abase_) + (uint32_t)s_ * 2048u;                    \
        uint32_t slabW_ = sW0 + (uint32_t)((kc_) * 8 + s_ + 32) * 2048u;      \
        ldsm_x4(af[buf][0], af[buf][1], af[buf][2], af[buf][3],               \
                slabA_ + aterm + ((((uint32_t)(2 * h_ + laneq)) ^ aswz) << 4));\
        uint32_t segw_ = (uint32_t)(2 * h_ + laneh);                          \
        ldsm_x4(bfA[buf][0][0], bfA[buf][0][1], bfA[buf][1][0], bfA[buf][1][1],\
                slabW_ + wterm[0] + ((segw_ ^ wswz[0]) << 4));                \
        ldsm_x4(bfA[buf][2][0], bfA[buf][2][1], bfA[buf][3][0], bfA[buf][3][1],\
                slabW_ + wterm[1] + ((segw_ ^ wswz[1]) << 4));                \
    } while (0)

    // xproj prefetch for t = 0
    float xp0, xp1, xp2, xp3;
    {
        const float* xp = g_xproj + ((size_t)(cb * T_ + 0)) * G4 + uu;
        xp0 = xp[0]; xp1 = xp[1024]; xp2 = xp[2048]; xp3 = xp[3072];
    }

    for (int t = 0; t < T_; t++) {
        const __nv_bfloat16* Abase =
            (t == 0) ? (g_A0 + lr * KA)
                     : (g_A2 + ((size_t)(lr * T_ + (t - 1))) * KA);
        const uint4* arow = (const uint4*)Abase;

        float acc[4][4];
#pragma unroll
        for (int i = 0; i < 4; i++)
#pragma unroll
            for (int q = 0; q < 4; q++) acc[i][q] = 0.f;

        uint4 va[4];
        // load + store chunk 0
#pragma unroll
        for (int j = 0; j < 4; j++) va[j] = arow[le + j * 8];
#pragma unroll
        for (int j = 0; j < 4; j++) {
            int cu4 = le + j * 8;
            int s = cu4 >> 2, q = (cu4 & 3) * 4;
            *(uint4*)&sA[s * 512 + lr * 16 + (q ^ lsw)] = va[j];
        }
        // load chunk 1
#pragma unroll
        for (int j = 0; j < 4; j++) va[j] = arow[32 + le + j * 8];
        __syncthreads();

        for (int kc = 0; kc < 8; kc++) {
            int p = kc & 1;
            if (kc < 7) {
                uint32_t boff = (uint32_t)(p ^ 1) * 4096u;
#pragma unroll
                for (int j = 0; j < 4; j++) {
                    int cu4 = le + j * 8;
                    int s = cu4 >> 2, q = (cu4 & 3) * 4;
                    *(uint4*)&sA[boff + s * 512 + lr * 16 + (q ^ lsw)] = va[j];
                }
                if (kc < 6) {
#pragma unroll
                    for (int j = 0; j < 4; j++)
                        va[j] = arow[(kc + 2) * 32 + le + j * 8];
                }
            }
            uint32_t abase = sA0 + (uint32_t)p * 16384u;
            uint32_t af[2][4], bfA[2][4][2];
            LOADFRAG(0, kc, 0, abase);
#pragma unroll
            for (int jj = 0; jj < 4; jj++) {
                if (jj < 3) LOADFRAG((jj + 1) & 1, kc, jj + 1, abase);
                int cur = jj & 1;
                if (kc < 4) {
                    // extra mma group with W slab a16 (lower half)
                    int j16 = jj * 4 + wk;
                    int s = j16 >> 1, h = j16 & 1;
                    uint32_t slabW0b = sW0 + (uint32_t)(kc * 8 + s) * 2048u;
                    uint32_t segw = (uint32_t)(2 * h + laneh);
                    uint32_t bfB[4][2];
                    ldsm_x4(bfB[0][0], bfB[0][1], bfB[1][0], bfB[1][1],
                            slabW0b + wterm[0] + ((segw ^ wswz[0]) << 4));
                    ldsm_x4(bfB[2][0], bfB[2][1], bfB[3][0], bfB[3][1],
                            slabW0b + wterm[1] + ((segw ^ wswz[1]) << 4));
#pragma unroll
                    for (int nt = 0; nt < 4; nt++)
                        mma_bf16(acc[nt], af[cur], bfA[cur][nt]);
#pragma unroll
                    for (int nt = 0; nt < 4; nt++)
                        mma_bf16(acc[nt], af[cur], bfB[nt]);
                } else {
#pragma unroll
                    for (int nt = 0; nt < 4; nt++)
                        mma_bf16(acc[nt], af[cur], bfA[cur][nt]);
                }
            }
            __syncthreads();
        }

#pragma unroll
        for (int nt = 0; nt < 4; nt++) {
#pragma unroll
            for (int i2 = 0; i2 < 2; i2++) {
                int m = wm * 16 + g + i2 * 8;
                int n = nt * 8 + 2 * tig;
                Csum[(wk * 32 + m) * 33 + n]     = acc[nt][i2 * 2];
                Csum[(wk * 32 + m) * 33 + n + 1] = acc[nt][i2 * 2 + 1];
            }
        }
        __syncthreads();

        {
            float gate[4];
#pragma unroll
            for (int g4 = 0; g4 < 4; g4++) {
                int n = g4 * 8 + cu;
                gate[g4] = Csum[(0 * 32 + cb) * 33 + n] + Csum[(1 * 32 + cb) * 33 + n]
                         + Csum[(2 * 32 + cb) * 33 + n] + Csum[(3 * 32 + cb) * 33 + n];
            }
            gate[0] += xp0; gate[1] += xp1; gate[2] += xp2; gate[3] += xp3;
            float cn = sigmoidf_(gate[1]) * creg + sigmoidf_(gate[0]) * tanhf(gate[2]);
            float hn = sigmoidf_(gate[3]) * tanhf(cn);
            creg = cn;
            __nv_bfloat16 hi = __float2bfloat16(hn);
            __nv_bfloat16 lo = __float2bfloat16(hn - __bfloat162float(hi));
            __nv_bfloat16* r = g_A2 + ((size_t)(cb * T_ + t)) * KA;
            r[uu] = hi; r[uu + 1024] = lo;
        }
        if (t + 1 < T_) {
            const float* xp = g_xproj + ((size_t)(cb * T_ + t + 1)) * G4 + uu;
            xp0 = xp[0]; xp1 = xp[1024]; xp2 = xp[2048]; xp3 = xp[3072];
        }
        __threadfence();
        GRIDBAR();
    }
#undef GRIDBAR
#undef LOADFRAG
}

// ---------------- launcher ---------------------------------------------------------
extern "C" void kernel_launch(void* const* d_in, const int* in_sizes, int n_in,
                              void* d_out, int out_size) {
    const float* features = (const float*)d_in[0];
    const int*   reports  = (const int*)d_in[1];
    const float* fc_W     = (const float*)d_in[2];
    const float* fc_b     = (const float*)d_in[3];
    const float* emb      = (const float*)d_in[4];
    const float* W_ih     = (const float*)d_in[5];
    const float* W_hh     = (const float*)d_in[6];
    const float* b_ih     = (const float*)d_in[7];
    const float* b_hh     = (const float*)d_in[8];
    const float* Wv       = (const float*)d_in[9];
    const float* bv       = (const float*)d_in[10];
    float* out = (float*)d_out;

    float *xproj_p, *bsum_p;
    __nv_bfloat16 *A2_p, *B2_p, *E2_p, *I2_p;
    int* idx_p;
    cudaGetSymbolAddress((void**)&xproj_p,  g_xproj);
    cudaGetSymbolAddress((void**)&bsum_p,   g_bsum);
    cudaGetSymbolAddress((void**)&idx_p,    g_idx);
    cudaGetSymbolAddress((void**)&A2_p,     g_A2);
    cudaGetSymbolAddress((void**)&B2_p,     g_B2);
    cudaGetSymbolAddress((void**)&E2_p,     g_E2);
    cudaGetSymbolAddress((void**)&I2_p,     g_I2);

    cudaFuncSetAttribute(lstm_persistent,
                         cudaFuncAttributeMaxDynamicSharedMemorySize, 229376);

    // #1: fused bf16 splits
    int convN = NW_ + NWH + NEM + NWI;
    conv_all_kernel<<<(convN + 255) / 256, 256>>>(Wv, W_hh, emb, W_ih);

    // #2: pooling + prep
    pool_prep_kernel<<<273, 256>>>(features, reports, b_ih, b_hh);

    // #3: xproj = emb[idx] @ W_ih^T + bsum
    mma_gemm_nt<KE, KE, true><<<dim3((B_ * T_) / 128, G4 / 128), 256>>>(
        E2_p, I2_p, bsum_p, xproj_p, G4, idx_p);

    // #4: persistent tensor-core LSTM
    lstm_persistent<<<NBLK, 256, 229376>>>(fc_W, fc_b);

    // #5: output projection (A stored [hi|lo], B [hi|lo|hi])
    mma_gemm_nt<KC, KA, false><<<dim3((B_ * T_) / 128, V_ / 128), 256>>>(
        A2_p, B2_p, bv, out, V_, nullptr);
}

// round 10
// speedup vs baseline: 1.5068x; 1.0183x over previous
#include <cuda_runtime.h>
#include <cuda_bf16.h>
#include <math.h>
#include <stdint.h>

#define B_  32
#define T_  128
#define V_  16000
#define E_  512
#define H_  1024
#define F_  2048
#define G4  4096   // 4*H
#define KC  3072   // 3*H contraction length (B-side [hi|lo|hi])
#define KA  2048   // A-side storage [hi|lo]
#define KE  1536   // 3*E (xproj, both sides stored full)
#define NBLK 128   // persistent LSTM blocks

// ---------------- scratch (device globals: no allocation allowed) ----------
__device__ float g_pooled[B_ * F_];
__device__ float g_bsum[G4];
__device__ int   g_idx[B_ * T_];
__device__ float g_xproj[(size_t)B_ * T_ * G4];        // 67 MB
__device__ __nv_bfloat16 g_A2[(size_t)B_ * T_ * KA];   // 16.8 MB [hi|lo]
__device__ __nv_bfloat16 g_B2[(size_t)V_ * KC];        // 98 MB  [hi|lo|hi]
__device__ __nv_bfloat16 g_W2[(size_t)G4 * KC];        // 25 MB  [hi|lo|hi]
__device__ __nv_bfloat16 g_E2[(size_t)V_ * KE];        // 49 MB  [hi|hi|lo]
__device__ __nv_bfloat16 g_I2[(size_t)G4 * KE];        // 12.6MB [hi|lo|hi]
__device__ __nv_bfloat16 g_A0[B_ * KA];                // h0 split [hi|lo]
__device__ unsigned int  g_barcnt;

// ---------------- fused bf16 split conversions (launch #1) --------------------
#define NW_  (V_ * H_)
#define NWH  (G4 * H_)
#define NEM  (V_ * E_)
#define NWI  (G4 * E_)
__global__ void conv_all_kernel(const float* __restrict__ Wv,
                                const float* __restrict__ W_hh,
                                const float* __restrict__ emb,
                                const float* __restrict__ W_ih) {
    int i = blockIdx.x * blockDim.x + threadIdx.x;
    const float* S;
    __nv_bfloat16* D;
    int li, sec, style;
    if (i < NW_) {
        S = Wv; D = g_B2; li = i; sec = 1024; style = 1;
    } else if (i < NW_ + NWH) {
        S = W_hh; D = g_W2; li = i - NW_; sec = 1024; style = 1;
    } else if (i < NW_ + NWH + NEM) {
        S = emb; D = g_E2; li = i - NW_ - NWH; sec = 512; style = 0;
    } else if (i < NW_ + NWH + NEM + NWI) {
        S = W_ih; D = g_I2; li = i - NW_ - NWH - NEM; sec = 512; style = 1;
    } else return;
    float x = S[li];
    int m = (sec == 1024) ? (li >> 10) : (li >> 9);
    int k = li & (sec - 1);
    __nv_bfloat16 hi = __float2bfloat16(x);
    __nv_bfloat16 lo = __float2bfloat16(x - __bfloat162float(hi));
    __nv_bfloat16* r = D + (size_t)m * (3 * sec);
    if (style == 0) { r[k] = hi; r[k + sec] = hi; r[k + 2 * sec] = lo; }
    else            { r[k] = hi; r[k + sec] = lo; r[k + 2 * sec] = hi; }
}

// ---------------- pooling + prep fused (launch #2) -----------------------------
__global__ void pool_prep_kernel(const float* __restrict__ feat,
                                 const int* __restrict__ reports,
                                 const float* __restrict__ b_ih,
                                 const float* __restrict__ b_hh) {
    int bid = blockIdx.x, tid = threadIdx.x;
    if (bid < 256) {
        int i = bid * 256 + tid;
        const float* p = feat + (size_t)i * 49;
        float s = 0.f;
#pragma unroll
        for (int k = 0; k < 49; k++) s += p[k];
        g_pooled[i] = s * (1.0f / 49.0f);
    } else {
        int j = (bid - 256) * 256 + tid;
        if (j == 0) g_barcnt = 0u;
        if (j < G4) g_bsum[j] = b_ih[j] + b_hh[j];
        if (j < B_ * T_) g_idx[j] = ((j & (T_ - 1)) == 0) ? 1 : reports[j - 1];
    }
}

// ---------------- mma / ldmatrix helpers ----------------------------------------
__device__ __forceinline__ uint32_t smem_u32(const void* p) {
    uint32_t a;
    asm("{ .reg .u64 t; cvta.to.shared.u64 t, %1; cvt.u32.u64 %0, t; }"
        : "=r"(a) : "l"(p));
    return a;
}
__device__ __forceinline__ void mma_bf16(float* d, const uint32_t* a,
                                         const uint32_t* b) {
    asm volatile(
        "mma.sync.aligned.m16n8k16.row.col.f32.bf16.bf16.f32 "
        "{%0,%1,%2,%3}, {%4,%5,%6,%7}, {%8,%9}, {%0,%1,%2,%3};"
        : "+f"(d[0]), "+f"(d[1]), "+f"(d[2]), "+f"(d[3])
        : "r"(a[0]), "r"(a[1]), "r"(a[2]), "r"(a[3]), "r"(b[0]), "r"(b[1]));
}
__device__ __forceinline__ void ldsm_x4(uint32_t& r0, uint32_t& r1,
                                        uint32_t& r2, uint32_t& r3,
                                        uint32_t addr) {
    asm volatile("ldmatrix.sync.aligned.m8n8.x4.shared.b16 {%0,%1,%2,%3}, [%4];"
                 : "=r"(r0), "=r"(r1), "=r"(r2), "=r"(r3) : "r"(addr));
}
__device__ __forceinline__ float sigmoidf_(float x) {
    return 1.f / (1.f + expf(-x));
}

// ---------------- 128x128 bf16 mma GEMM (ldmatrix, 1 sync/chunk) ----------------
// KTOT = contraction length. AK = A row storage; chunks >= TH remap (A-hi reuse).
template <int KTOT, int AK, bool GATHER>
__global__ void __launch_bounds__(256, 2)
mma_gemm_nt(const __nv_bfloat16* __restrict__ A2,
            const __nv_bfloat16* __restrict__ B2,
            const float* __restrict__ bias,
            float* __restrict__ C, int ncols,
            const int* __restrict__ ridx) {
    __shared__ uint32_t sA[2][128 * 16];
    __shared__ uint32_t sB[2][128 * 16];

    const int NK = KTOT / 32;
    const int TH = (KTOT - AK) / 32;   // 0 when AK==KTOT
    int tid = threadIdx.x;
    int lane = tid & 31, w = tid >> 5;
    int g = lane >> 2, tig = lane & 3;
    int wm = w >> 2, wn = w & 3;
    int laneq = lane >> 4;
    int laneh = (lane >> 3) & 1;
    int lane15 = lane & 15, lane7 = lane & 7;

    int m0 = blockIdx.x * 128;
    int n0 = blockIdx.y * 128;

    uint32_t sA0 = smem_u32(sA), sB0 = smem_u32(sB);

    int lrow = tid >> 1;
    int lhalf = tid & 1;
    int ar = GATHER ? ridx[m0 + lrow] : (m0 + lrow);
    const uint4* pa = (const uint4*)(A2 + (size_t)ar * AK) + lhalf * 2;
    const uint4* pb = (const uint4*)(B2 + (size_t)(n0 + lrow) * KTOT) + lhalf * 2;
    int sw = lrow & 6;
    int st0 = (lrow << 4) + (((lhalf * 4 + 0) ^ sw) << 1);
    int st1 = (lrow << 4) + (((lhalf * 4 + 2) ^ sw) << 1);

    uint32_t aterm[4], aswz[4];
#pragma unroll
    for (int mt = 0; mt < 4; mt++) {
        int rowA = wm * 64 + mt * 16 + lane15;
        aterm[mt] = (uint32_t)rowA * 64u;
        aswz[mt] = (uint32_t)((rowA & 6) >> 1);
    }
    uint32_t bterm[2], bswz[2];
#pragma unroll
    for (int ntp = 0; ntp < 2; ntp++) {
        int rowB = wn * 32 + (2 * ntp + laneq) * 8 + lane7;
        bterm[ntp] = (uint32_t)rowB * 64u;
        bswz[ntp] = (uint32_t)((rowB & 6) >> 1);
    }

    float acc[4][4][4];
#pragma unroll
    for (int i = 0; i < 4; i++)
#pragma unroll
        for (int j = 0; j < 4; j++)
#pragma unroll
            for (int q = 0; q < 4; q++) acc[i][j][q] = 0.f;

#define AIDX(kn_) ((TH == 0) ? (kn_) : (((kn_) < TH) ? (kn_) : (kn_) - TH))

    // prolog: chunk 0 -> buf0; prefetch chunk 1 into regs
    uint4 ra0 = pa[0], ra1 = pa[1];
    uint4 rb0 = pb[0], rb1 = pb[1];
    *(uint4*)&sA[0][st0] = ra0;
    *(uint4*)&sA[0][st1] = ra1;
    *(uint4*)&sB[0][st0] = rb0;
    *(uint4*)&sB[0][st1] = rb1;
    {
        int a1 = AIDX(1);
        ra0 = pa[a1 * 4 + 0]; ra1 = pa[a1 * 4 + 1];
        rb0 = pb[4];          rb1 = pb[5];
    }
    __syncthreads();

    for (int kc = 0; kc < NK; kc++) {
        int p = kc & 1;
        // store chunk kc+1 into buffer p^1 (its readers synced out last iter)
        if (kc + 1 < NK) {
            *(uint4*)&sA[p ^ 1][st0] = ra0;
            *(uint4*)&sA[p ^ 1][st1] = ra1;
            *(uint4*)&sB[p ^ 1][st0] = rb0;
            *(uint4*)&sB[p ^ 1][st1] = rb1;
            if (kc + 2 < NK) {
                int kn = kc + 2;
                int akc = AIDX(kn);
                ra0 = pa[akc * 4 + 0]; ra1 = pa[akc * 4 + 1];
                rb0 = pb[kn * 4 + 0];  rb1 = pb[kn * 4 + 1];
            }
        }

        uint32_t abase = sA0 + (uint32_t)p * 8192u;
        uint32_t bbase = sB0 + (uint32_t)p * 8192u;
#pragma unroll
        for (int ks = 0; ks < 2; ks++) {
            uint32_t bf[4][2];
            {
                uint32_t segb = (uint32_t)(2 * ks + laneh);
                ldsm_x4(bf[0][0], bf[0][1], bf[1][0], bf[1][1],
                        bbase + bterm[0] + (((segb ^ bswz[0])) << 4));
                ldsm_x4(bf[2][0], bf[2][1], bf[3][0], bf[3][1],
                        bbase + bterm[1] + (((segb ^ bswz[1])) << 4));
            }
            uint32_t sega = (uint32_t)(2 * ks + laneq);
#pragma unroll
            for (int mt = 0; mt < 4; mt++) {
                uint32_t af[4];
                ldsm_x4(af[0], af[1], af[2], af[3],
                        abase + aterm[mt] + (((sega ^ aswz[mt])) << 4));
#pragma unroll
                for (int nt = 0; nt < 4; nt++)
                    mma_bf16(acc[mt][nt], af, bf[nt]);
            }
        }
        __syncthreads();   // single barrier: protects p reads + p^1 writes
    }
#undef AIDX

#pragma unroll
    for (int mt = 0; mt < 4; mt++) {
#pragma unroll
        for (int i2 = 0; i2 < 2; i2++) {
            int row = m0 + wm * 64 + mt * 16 + g + i2 * 8;
            float* crow = C + (size_t)row * ncols;
#pragma unroll
            for (int nt = 0; nt < 4; nt++) {
                int col = n0 + wn * 32 + nt * 8 + 2 * tig;
                float b0 = __ldg(&bias[col]);
                float b1 = __ldg(&bias[col + 1]);
                crow[col]     = acc[mt][nt][i2 * 2]     + b0;
                crow[col + 1] = acc[mt][nt][i2 * 2 + 1] + b1;
            }
        }
    }
}

// ---------------- persistent tensor-core LSTM (launch #4) -----------------------
// A stored [hi|lo]; W [hi|lo|hi]. CG-style release/acquire grid barrier
// (no per-thread gpu-scope fence -> no per-step L1D flush).
__global__ void __launch_bounds__(256, 1)
lstm_persistent(const float* __restrict__ fc_W, const float* __restrict__ fc_b) {
    extern __shared__ char smem[];
    uint32_t* sW = (uint32_t*)smem;                    // 96 slabs x 2048B = 192KB
    uint32_t* sA = (uint32_t*)(smem + 196608);         // 2 x 16KB
    float*  Csum = (float*)(smem + 196608);            // overlay (16.9KB)

    int tid = threadIdx.x;
    int lane = tid & 31, w = tid >> 5;
    int g = lane >> 2, tig = lane & 3;
    int wm = w >> 2, wk = w & 3;
    int u0 = blockIdx.x * 8;
    int laneq = lane >> 4;
    int laneh = (lane >> 3) & 1;
    int lane15 = lane & 15, lane7 = lane & 7;

    uint32_t sW0 = smem_u32(sW), sA0 = smem_u32(sA);

    // ---- one-time: stage W slice [32 rows x 3072] ----
    {
        int r = tid >> 3, e = tid & 7;
        int grow = ((r >> 3) << 10) + u0 + (r & 7);
        const uint4* wrow = (const uint4*)(g_W2 + (size_t)grow * KC);
        int sw = (r & 6) << 1;
#pragma unroll 4
        for (int j = 0; j < 48; j++) {
            int idx = e + j * 8;
            uint4 v = wrow[idx];
            int s = idx >> 2, q = (idx & 3) * 4;
            *(uint4*)&sW[s * 512 + r * 16 + (q ^ sw)] = v;
        }
    }

    // ---- fc prologue: this block's 16 init columns (8 h + 8 c) ----
    int cb = tid >> 3, cu = tid & 7;
    int uu = u0 + cu;
    float acch = fc_b[uu], accc = fc_b[H_ + uu];
    {
        const float4* pp  = (const float4*)(g_pooled + cb * F_);
        const float4* pwh = (const float4*)(fc_W + (size_t)uu * F_);
        const float4* pwc = (const float4*)(fc_W + (size_t)(H_ + uu) * F_);
#pragma unroll 4
        for (int k = 0; k < F_ / 4; k++) {
            float4 p = pp[k], a = pwh[k], b = pwc[k];
            acch += p.x * a.x + p.y * a.y + p.z * a.z + p.w * a.w;
            accc += p.x * b.x + p.y * b.y + p.z * b.z + p.w * b.w;
        }
    }
    float creg = accc;
    {
        __nv_bfloat16 hi = __float2bfloat16(acch);
        __nv_bfloat16 lo = __float2bfloat16(acch - __bfloat162float(hi));
        __nv_bfloat16* r = g_A0 + cb * KA;
        r[uu] = hi; r[uu + 1024] = lo;
    }

    unsigned epoch = 0;
    unsigned long long barp;
    {
        unsigned int* bp;
        asm("cvta.global.u64 %0, %1;" : "=l"(barp) : "l"(&g_barcnt));
    }
    // CG-style grid barrier: bar.sync gives intra-block HB; release/acquire
    // extends across blocks. No gpu-scope fence (no L1D flush).
#define GRIDBAR() do {                                                       \
        __syncthreads();                                                     \
        epoch++;                                                             \
        if (tid == 0) {                                                      \
            asm volatile("red.release.gpu.global.add.u32 [%0], %1;"          \
                         :: "l"(barp), "r"(1u) : "memory");                  \
            unsigned v_;                                                     \
            do {                                                             \
                asm volatile("ld.acquire.gpu.global.u32 %0, [%1];"           \
                             : "=r"(v_) : "l"(barp) : "memory");             \
            } while (v_ < epoch * (unsigned)NBLK);                           \
        }                                                                    \
        __syncthreads();                                                     \
    } while (0)

    GRIDBAR();

    int lr = tid >> 3, le = tid & 7;
    int lsw = (lr & 6) << 1;

    // ldmatrix address invariants
    uint32_t aterm, aswz;
    {
        int rowA = wm * 16 + lane15;
        aterm = (uint32_t)rowA * 64u;
        aswz = (uint32_t)((rowA & 6) >> 1);
    }
    uint32_t wterm[2], wswz[2];
#pragma unroll
    for (int ntp = 0; ntp < 2; ntp++) {
        int rowW = (2 * ntp + laneq) * 8 + lane7;
        wterm[ntp] = (uint32_t)rowW * 64u;
        wswz[ntp] = (uint32_t)((rowW & 6) >> 1);
    }

#define LOADFRAG(buf, kc_, jj_, abase_) do {                                  \
        int j16_ = (jj_) * 4 + wk;                                            \
        int s_ = j16_ >> 1, h_ = j16_ & 1;                                    \
        uint32_t slabA_ = (abase_) + (uint32_t)s_ * 2048u;                    \
        uint32_t slabW_ = sW0 + (uint32_t)((kc_) * 8 + s_ + 32) * 2048u;      \
        ldsm_x4(af[buf][0], af[buf][1], af[buf][2], af[buf][3],               \
                slabA_ + aterm + ((((uint32_t)(2 * h_ + laneq)) ^ aswz) << 4));\
        uint32_t segw_ = (uint32_t)(2 * h_ + laneh);                          \
        ldsm_x4(bfA[buf][0][0], bfA[buf][0][1], bfA[buf][1][0], bfA[buf][1][1],\
                slabW_ + wterm[0] + ((segw_ ^ wswz[0]) << 4));                \
        ldsm_x4(bfA[buf][2][0], bfA[buf][2][1], bfA[buf][3][0], bfA[buf][3][1],\
                slabW_ + wterm[1] + ((segw_ ^ wswz[1]) << 4));                \
    } while (0)

    // xproj prefetch for t = 0
    float xp0, xp1, xp2, xp3;
    {
        const float* xp = g_xproj + ((size_t)(cb * T_ + 0)) * G4 + uu;
        xp0 = xp[0]; xp1 = xp[1024]; xp2 = xp[2048]; xp3 = xp[3072];
    }

    for (int t = 0; t < T_; t++) {
        const __nv_bfloat16* Abase =
            (t == 0) ? (g_A0 + lr * KA)
                     : (g_A2 + ((size_t)(lr * T_ + (t - 1))) * KA);
        const uint4* arow = (const uint4*)Abase;

        float acc[4][4];
#pragma unroll
        for (int i = 0; i < 4; i++)
#pragma unroll
            for (int q = 0; q < 4; q++) acc[i][q] = 0.f;

        uint4 va[4];
#pragma unroll
        for (int j = 0; j < 4; j++) va[j] = arow[le + j * 8];
#pragma unroll
        for (int j = 0; j < 4; j++) {
            int cu4 = le + j * 8;
            int s = cu4 >> 2, q = (cu4 & 3) * 4;
            *(uint4*)&sA[s * 512 + lr * 16 + (q ^ lsw)] = va[j];
        }
#pragma unroll
        for (int j = 0; j < 4; j++) va[j] = arow[32 + le + j * 8];
        __syncthreads();

        for (int kc = 0; kc < 8; kc++) {
            int p = kc & 1;
            if (kc < 7) {
                uint32_t boff = (uint32_t)(p ^ 1) * 4096u;
#pragma unroll
                for (int j = 0; j < 4; j++) {
                    int cu4 = le + j * 8;
                    int s = cu4 >> 2, q = (cu4 & 3) * 4;
                    *(uint4*)&sA[boff + s * 512 + lr * 16 + (q ^ lsw)] = va[j];
                }
                if (kc < 6) {
#pragma unroll
                    for (int j = 0; j < 4; j++)
                        va[j] = arow[(kc + 2) * 32 + le + j * 8];
                }
            }
            uint32_t abase = sA0 + (uint32_t)p * 16384u;
            uint32_t af[2][4], bfA[2][4][2];
            LOADFRAG(0, kc, 0, abase);
#pragma unroll
            for (int jj = 0; jj < 4; jj++) {
                if (jj < 3) LOADFRAG((jj + 1) & 1, kc, jj + 1, abase);
                int cur = jj & 1;
                if (kc < 4) {
                    int j16 = jj * 4 + wk;
                    int s = j16 >> 1, h = j16 & 1;
                    uint32_t slabW0b = sW0 + (uint32_t)(kc * 8 + s) * 2048u;
                    uint32_t segw = (uint32_t)(2 * h + laneh);
                    uint32_t bfB[4][2];
                    ldsm_x4(bfB[0][0], bfB[0][1], bfB[1][0], bfB[1][1],
                            slabW0b + wterm[0] + ((segw ^ wswz[0]) << 4));
                    ldsm_x4(bfB[2][0], bfB[2][1], bfB[3][0], bfB[3][1],
                            slabW0b + wterm[1] + ((segw ^ wswz[1]) << 4));
#pragma unroll
                    for (int nt = 0; nt < 4; nt++)
                        mma_bf16(acc[nt], af[cur], bfA[cur][nt]);
#pragma unroll
                    for (int nt = 0; nt < 4; nt++)
                        mma_bf16(acc[nt], af[cur], bfB[nt]);
                } else {
#pragma unroll
                    for (int nt = 0; nt < 4; nt++)
                        mma_bf16(acc[nt], af[cur], bfA[cur][nt]);
                }
            }
            __syncthreads();
        }

#pragma unroll
        for (int nt = 0; nt < 4; nt++) {
#pragma unroll
            for (int i2 = 0; i2 < 2; i2++) {
                int m = wm * 16 + g + i2 * 8;
                int n = nt * 8 + 2 * tig;
                Csum[(wk * 32 + m) * 33 + n]     = acc[nt][i2 * 2];
                Csum[(wk * 32 + m) * 33 + n + 1] = acc[nt][i2 * 2 + 1];
            }
        }
        __syncthreads();

        {
            float gate[4];
#pragma unroll
            for (int g4 = 0; g4 < 4; g4++) {
                int n = g4 * 8 + cu;
                gate[g4] = Csum[(0 * 32 + cb) * 33 + n] + Csum[(1 * 32 + cb) * 33 + n]
                         + Csum[(2 * 32 + cb) * 33 + n] + Csum[(3 * 32 + cb) * 33 + n];
            }
            gate[0] += xp0; gate[1] += xp1; gate[2] += xp2; gate[3] += xp3;
            float cn = sigmoidf_(gate[1]) * creg + sigmoidf_(gate[0]) * tanhf(gate[2]);
            float hn = sigmoidf_(gate[3]) * tanhf(cn);
            creg = cn;
            __nv_bfloat16 hi = __float2bfloat16(hn);
            __nv_bfloat16 lo = __float2bfloat16(hn - __bfloat162float(hi));
            __nv_bfloat16* r = g_A2 + ((size_t)(cb * T_ + t)) * KA;
            r[uu] = hi; r[uu + 1024] = lo;
        }
        if (t + 1 < T_) {
            const float* xp = g_xproj + ((size_t)(cb * T_ + t + 1)) * G4 + uu;
            xp0 = xp[0]; xp1 = xp[1024]; xp2 = xp[2048]; xp3 = xp[3072];
        }
        GRIDBAR();
    }
#undef GRIDBAR
#undef LOADFRAG
}

// ---------------- launcher ---------------------------------------------------------
extern "C" void kernel_launch(void* const* d_in, const int* in_sizes, int n_in,
                              void* d_out, int out_size) {
    const float* features = (const float*)d_in[0];
    const int*   reports  = (const int*)d_in[1];
    const float* fc_W     = (const float*)d_in[2];
    const float* fc_b     = (const float*)d_in[3];
    const float* emb      = (const float*)d_in[4];
    const float* W_ih     = (const float*)d_in[5];
    const float* W_hh     = (const float*)d_in[6];
    const float* b_ih     = (const float*)d_in[7];
    const float* b_hh     = (const float*)d_in[8];
    const float* Wv       = (const float*)d_in[9];
    const float* bv       = (const float*)d_in[10];
    float* out = (float*)d_out;

    float *xproj_p, *bsum_p;
    __nv_bfloat16 *A2_p, *B2_p, *E2_p, *I2_p;
    int* idx_p;
    cudaGetSymbolAddress((void**)&xproj_p,  g_xproj);
    cudaGetSymbolAddress((void**)&bsum_p,   g_bsum);
    cudaGetSymbolAddress((void**)&idx_p,    g_idx);
    cudaGetSymbolAddress((void**)&A2_p,     g_A2);
    cudaGetSymbolAddress((void**)&B2_p,     g_B2);
    cudaGetSymbolAddress((void**)&E2_p,     g_E2);
    cudaGetSymbolAddress((void**)&I2_p,     g_I2);

    cudaFuncSetAttribute(lstm_persistent,
                         cudaFuncAttributeMaxDynamicSharedMemorySize, 229376);

    // #1: fused bf16 splits
    int convN = NW_ + NWH + NEM + NWI;
    conv_all_kernel<<<(convN + 255) / 256, 256>>>(Wv, W_hh, emb, W_ih);

    // #2: pooling + prep
    pool_prep_kernel<<<273, 256>>>(features, reports, b_ih, b_hh);

    // #3: xproj = emb[idx] @ W_ih^T + bsum
    mma_gemm_nt<KE, KE, true><<<dim3((B_ * T_) / 128, G4 / 128), 256>>>(
        E2_p, I2_p, bsum_p, xproj_p, G4, idx_p);

    // #4: persistent tensor-core LSTM
    lstm_persistent<<<NBLK, 256, 229376>>>(fc_W, fc_b);

    // #5: output projection (A stored [hi|lo], B [hi|lo|hi])
    mma_gemm_nt<KC, KA, false><<<dim3((B_ * T_) / 128, V_ / 128), 256>>>(
        A2_p, B2_p, bv, out, V_, nullptr);
}

// round 11
// speedup vs baseline: 1.6301x; 1.0818x over previous
#include <cuda_runtime.h>
#include <cuda_bf16.h>
#include <math.h>
#include <stdint.h>

#define B_  32
#define T_  128
#define V_  16000
#define E_  512
#define H_  1024
#define F_  2048
#define G4  4096   // 4*H
#define KC  3072   // 3*H contraction length (B-side [hi|lo|hi])
#define KA  2048   // A-side storage [hi|lo]
#define KE  1536   // 3*E (xproj, both sides stored full)
#define NBLK 128   // persistent LSTM blocks

// ---------------- scratch (device globals: no allocation allowed) ----------
__device__ float g_pooled[B_ * F_];
__device__ float g_bsum[G4];
__device__ int   g_idx[B_ * T_];
__device__ float g_xproj[(size_t)B_ * T_ * G4];        // 67 MB
__device__ __nv_bfloat16 g_A2[(size_t)B_ * T_ * KA];   // 16.8 MB [hi|lo]
__device__ __nv_bfloat16 g_B2[(size_t)V_ * KC];        // 98 MB  [hi|lo|hi]
__device__ __nv_bfloat16 g_W2[(size_t)G4 * KC];        // 25 MB  [hi|lo|hi]
__device__ __nv_bfloat16 g_E2[(size_t)V_ * KE];        // 49 MB  [hi|hi|lo]
__device__ __nv_bfloat16 g_I2[(size_t)G4 * KE];        // 12.6MB [hi|lo|hi]
__device__ __nv_bfloat16 g_A0[B_ * KA];                // h0 split [hi|lo]
__device__ unsigned int  g_barcnt;

// ---------------- cp.async helpers ---------------------------------------------
#define CP_ASYNC16(dst, src) \
    asm volatile("cp.async.cg.shared.global [%0], [%1], 16;" \
                 :: "r"((uint32_t)(dst)), "l"(src))
#define CP_COMMIT() asm volatile("cp.async.commit_group;" ::: "memory")
#define CP_WAIT0()  asm volatile("cp.async.wait_group 0;" ::: "memory")
#define CP_WAIT1()  asm volatile("cp.async.wait_group 1;" ::: "memory")

// ---------------- fused bf16 split conversions (launch #1) --------------------
#define NW_  (V_ * H_)
#define NWH  (G4 * H_)
#define NEM  (V_ * E_)
#define NWI  (G4 * E_)
__global__ void conv_all_kernel(const float* __restrict__ Wv,
                                const float* __restrict__ W_hh,
                                const float* __restrict__ emb,
                                const float* __restrict__ W_ih) {
    int i = blockIdx.x * blockDim.x + threadIdx.x;
    const float* S;
    __nv_bfloat16* D;
    int li, sec, style;
    if (i < NW_) {
        S = Wv; D = g_B2; li = i; sec = 1024; style = 1;
    } else if (i < NW_ + NWH) {
        S = W_hh; D = g_W2; li = i - NW_; sec = 1024; style = 1;
    } else if (i < NW_ + NWH + NEM) {
        S = emb; D = g_E2; li = i - NW_ - NWH; sec = 512; style = 0;
    } else if (i < NW_ + NWH + NEM + NWI) {
        S = W_ih; D = g_I2; li = i - NW_ - NWH - NEM; sec = 512; style = 1;
    } else return;
    float x = S[li];
    int m = (sec == 1024) ? (li >> 10) : (li >> 9);
    int k = li & (sec - 1);
    __nv_bfloat16 hi = __float2bfloat16(x);
    __nv_bfloat16 lo = __float2bfloat16(x - __bfloat162float(hi));
    __nv_bfloat16* r = D + (size_t)m * (3 * sec);
    if (style == 0) { r[k] = hi; r[k + sec] = hi; r[k + 2 * sec] = lo; }
    else            { r[k] = hi; r[k + sec] = lo; r[k + 2 * sec] = hi; }
}

// ---------------- pooling + prep fused (launch #2) -----------------------------
__global__ void pool_prep_kernel(const float* __restrict__ feat,
                                 const int* __restrict__ reports,
                                 const float* __restrict__ b_ih,
                                 const float* __restrict__ b_hh) {
    int bid = blockIdx.x, tid = threadIdx.x;
    if (bid < 256) {
        int i = bid * 256 + tid;
        const float* p = feat + (size_t)i * 49;
        float s = 0.f;
#pragma unroll
        for (int k = 0; k < 49; k++) s += p[k];
        g_pooled[i] = s * (1.0f / 49.0f);
    } else {
        int j = (bid - 256) * 256 + tid;
        if (j == 0) g_barcnt = 0u;
        if (j < G4) g_bsum[j] = b_ih[j] + b_hh[j];
        if (j < B_ * T_) g_idx[j] = ((j & (T_ - 1)) == 0) ? 1 : reports[j - 1];
    }
}

// ---------------- mma / ldmatrix helpers ----------------------------------------
__device__ __forceinline__ uint32_t smem_u32(const void* p) {
    uint32_t a;
    asm("{ .reg .u64 t; cvta.to.shared.u64 t, %1; cvt.u32.u64 %0, t; }"
        : "=r"(a) : "l"(p));
    return a;
}
__device__ __forceinline__ void mma_bf16(float* d, const uint32_t* a,
                                         const uint32_t* b) {
    asm volatile(
        "mma.sync.aligned.m16n8k16.row.col.f32.bf16.bf16.f32 "
        "{%0,%1,%2,%3}, {%4,%5,%6,%7}, {%8,%9}, {%0,%1,%2,%3};"
        : "+f"(d[0]), "+f"(d[1]), "+f"(d[2]), "+f"(d[3])
        : "r"(a[0]), "r"(a[1]), "r"(a[2]), "r"(a[3]), "r"(b[0]), "r"(b[1]));
}
__device__ __forceinline__ void ldsm_x4(uint32_t& r0, uint32_t& r1,
                                        uint32_t& r2, uint32_t& r3,
                                        uint32_t addr) {
    asm volatile("ldmatrix.sync.aligned.m8n8.x4.shared.b16 {%0,%1,%2,%3}, [%4];"
                 : "=r"(r0), "=r"(r1), "=r"(r2), "=r"(r3) : "r"(addr));
}
__device__ __forceinline__ float sigmoidf_(float x) {
    return 1.f / (1.f + expf(-x));
}

// ---------------- 128x128 bf16 mma GEMM (cp.async 3-stage, ldmatrix) -----------
// KTOT = contraction length. AK = A row storage; chunks >= TH remap (A-hi reuse).
template <int KTOT, int AK, bool GATHER>
__global__ void __launch_bounds__(256, 2)
mma_gemm_nt(const __nv_bfloat16* __restrict__ A2,
            const __nv_bfloat16* __restrict__ B2,
            const float* __restrict__ bias,
            float* __restrict__ C, int ncols,
            const int* __restrict__ ridx) {
    __shared__ uint32_t sA[3][128 * 16];   // 8KB per stage
    __shared__ uint32_t sB[3][128 * 16];

    const int NK = KTOT / 32;
    const int TH = (KTOT - AK) / 32;   // 0 when AK==KTOT
    int tid = threadIdx.x;
    int lane = tid & 31, w = tid >> 5;
    int g = lane >> 2, tig = lane & 3;
    int wm = w >> 2, wn = w & 3;
    int laneq = lane >> 4;
    int laneh = (lane >> 3) & 1;
    int lane15 = lane & 15, lane7 = lane & 7;

    int m0 = blockIdx.x * 128;
    int n0 = blockIdx.y * 128;

    uint32_t sA0 = smem_u32(sA), sB0 = smem_u32(sB);

    int lrow = tid >> 1;
    int lhalf = tid & 1;
    int ar = GATHER ? ridx[m0 + lrow] : (m0 + lrow);
    const char* pa = (const char*)((const uint4*)(A2 + (size_t)ar * AK) + lhalf * 2);
    const char* pb = (const char*)((const uint4*)(B2 + (size_t)(n0 + lrow) * KTOT) + lhalf * 2);
    int sw = lrow & 6;
    uint32_t st0 = (uint32_t)(((lrow << 4) + (((lhalf * 4 + 0) ^ sw) << 1)) << 2);
    uint32_t st1 = (uint32_t)(((lrow << 4) + (((lhalf * 4 + 2) ^ sw) << 1)) << 2);

    uint32_t aterm[4], aswz[4];
#pragma unroll
    for (int mt = 0; mt < 4; mt++) {
        int rowA = wm * 64 + mt * 16 + lane15;
        aterm[mt] = (uint32_t)rowA * 64u;
        aswz[mt] = (uint32_t)((rowA & 6) >> 1);
    }
    uint32_t bterm[2], bswz[2];
#pragma unroll
    for (int ntp = 0; ntp < 2; ntp++) {
        int rowB = wn * 32 + (2 * ntp + laneq) * 8 + lane7;
        bterm[ntp] = (uint32_t)rowB * 64u;
        bswz[ntp] = (uint32_t)((rowB & 6) >> 1);
    }

    float acc[4][4][4];
#pragma unroll
    for (int i = 0; i < 4; i++)
#pragma unroll
        for (int j = 0; j < 4; j++)
#pragma unroll
            for (int q = 0; q < 4; q++) acc[i][j][q] = 0.f;

#define AIDX(kn_) ((TH == 0) ? (kn_) : (((kn_) < TH) ? (kn_) : (kn_) - TH))
#define GISSUE(kn_, st_) do {                                                \
        int akc_ = AIDX(kn_);                                                \
        const char* pa_ = pa + (size_t)akc_ * 64;                            \
        const char* pb_ = pb + (size_t)(kn_) * 64;                           \
        uint32_t ab_ = sA0 + (uint32_t)(st_) * 8192u;                        \
        uint32_t bb_ = sB0 + (uint32_t)(st_) * 8192u;                        \
        CP_ASYNC16(ab_ + st0, pa_);                                          \
        CP_ASYNC16(ab_ + st1, pa_ + 16);                                     \
        CP_ASYNC16(bb_ + st0, pb_);                                          \
        CP_ASYNC16(bb_ + st1, pb_ + 16);                                     \
        CP_COMMIT();                                                         \
    } while (0)

    // prologue: stage chunks 0, 1
    GISSUE(0, 0);
    GISSUE(1, 1);

    for (int kc = 0; kc < NK; kc++) {
        int st = kc % 3;
        if (kc + 1 < NK) { CP_WAIT1(); } else { CP_WAIT0(); }
        __syncthreads();
        if (kc + 2 < NK) GISSUE(kc + 2, (kc + 2) % 3);

        uint32_t abase = sA0 + (uint32_t)st * 8192u;
        uint32_t bbase = sB0 + (uint32_t)st * 8192u;
#pragma unroll
        for (int ks = 0; ks < 2; ks++) {
            uint32_t bf[4][2];
            {
                uint32_t segb = (uint32_t)(2 * ks + laneh);
                ldsm_x4(bf[0][0], bf[0][1], bf[1][0], bf[1][1],
                        bbase + bterm[0] + (((segb ^ bswz[0])) << 4));
                ldsm_x4(bf[2][0], bf[2][1], bf[3][0], bf[3][1],
                        bbase + bterm[1] + (((segb ^ bswz[1])) << 4));
            }
            uint32_t sega = (uint32_t)(2 * ks + laneq);
#pragma unroll
            for (int mt = 0; mt < 4; mt++) {
                uint32_t af[4];
                ldsm_x4(af[0], af[1], af[2], af[3],
                        abase + aterm[mt] + (((sega ^ aswz[mt])) << 4));
#pragma unroll
                for (int nt = 0; nt < 4; nt++)
                    mma_bf16(acc[mt][nt], af, bf[nt]);
            }
        }
    }
#undef GISSUE
#undef AIDX

#pragma unroll
    for (int mt = 0; mt < 4; mt++) {
#pragma unroll
        for (int i2 = 0; i2 < 2; i2++) {
            int row = m0 + wm * 64 + mt * 16 + g + i2 * 8;
            float* crow = C + (size_t)row * ncols;
#pragma unroll
            for (int nt = 0; nt < 4; nt++) {
                int col = n0 + wn * 32 + nt * 8 + 2 * tig;
                float b0 = __ldg(&bias[col]);
                float b1 = __ldg(&bias[col + 1]);
                crow[col]     = acc[mt][nt][i2 * 2]     + b0;
                crow[col + 1] = acc[mt][nt][i2 * 2 + 1] + b1;
            }
        }
    }
}

// ---------------- persistent tensor-core LSTM (launch #4) -----------------------
// A stored [hi|lo]; W [hi|lo|hi] in smem. cp.async A-chunk staging (2 buffers),
// CG-style release/acquire grid barrier.
__global__ void __launch_bounds__(256, 1)
lstm_persistent(const float* __restrict__ fc_W, const float* __restrict__ fc_b) {
    extern __shared__ char smem[];
    uint32_t* sW = (uint32_t*)smem;                    // 96 slabs x 2048B = 192KB
    uint32_t* sA = (uint32_t*)(smem + 196608);         // 2 x 16KB
    float*  Csum = (float*)(smem + 196608);            // overlay (16.9KB)

    int tid = threadIdx.x;
    int lane = tid & 31, w = tid >> 5;
    int g = lane >> 2, tig = lane & 3;
    int wm = w >> 2, wk = w & 3;
    int u0 = blockIdx.x * 8;
    int laneq = lane >> 4;
    int laneh = (lane >> 3) & 1;
    int lane15 = lane & 15, lane7 = lane & 7;

    uint32_t sW0 = smem_u32(sW), sA0 = smem_u32(sA);

    // ---- one-time: stage W slice [32 rows x 3072] ----
    {
        int r = tid >> 3, e = tid & 7;
        int grow = ((r >> 3) << 10) + u0 + (r & 7);
        const uint4* wrow = (const uint4*)(g_W2 + (size_t)grow * KC);
        int sw = (r & 6) << 1;
#pragma unroll 4
        for (int j = 0; j < 48; j++) {
            int idx = e + j * 8;
            uint4 v = wrow[idx];
            int s = idx >> 2, q = (idx & 3) * 4;
            *(uint4*)&sW[s * 512 + r * 16 + (q ^ sw)] = v;
        }
    }

    // ---- fc prologue: this block's 16 init columns (8 h + 8 c) ----
    int cb = tid >> 3, cu = tid & 7;
    int uu = u0 + cu;
    float acch = fc_b[uu], accc = fc_b[H_ + uu];
    {
        const float4* pp  = (const float4*)(g_pooled + cb * F_);
        const float4* pwh = (const float4*)(fc_W + (size_t)uu * F_);
        const float4* pwc = (const float4*)(fc_W + (size_t)(H_ + uu) * F_);
#pragma unroll 4
        for (int k = 0; k < F_ / 4; k++) {
            float4 p = pp[k], a = pwh[k], b = pwc[k];
            acch += p.x * a.x + p.y * a.y + p.z * a.z + p.w * a.w;
            accc += p.x * b.x + p.y * b.y + p.z * b.z + p.w * b.w;
        }
    }
    float creg = accc;
    {
        __nv_bfloat16 hi = __float2bfloat16(acch);
        __nv_bfloat16 lo = __float2bfloat16(acch - __bfloat162float(hi));
        __nv_bfloat16* r = g_A0 + cb * KA;
        r[uu] = hi; r[uu + 1024] = lo;
    }

    unsigned epoch = 0;
    unsigned long long barp;
    asm("cvta.global.u64 %0, %1;" : "=l"(barp) : "l"(&g_barcnt));
#define GRIDBAR() do {                                                       \
        __syncthreads();                                                     \
        epoch++;                                                             \
        if (tid == 0) {                                                      \
            asm volatile("red.release.gpu.global.add.u32 [%0], %1;"          \
                         :: "l"(barp), "r"(1u) : "memory");                  \
            unsigned v_;                                                     \
            do {                                                             \
                asm volatile("ld.acquire.gpu.global.u32 %0, [%1];"           \
                             : "=r"(v_) : "l"(barp) : "memory");             \
            } while (v_ < epoch * (unsigned)NBLK);                           \
        }                                                                    \
        __syncthreads();                                                     \
    } while (0)

    GRIDBAR();

    int lr = tid >> 3, le = tid & 7;
    int lsw = (lr & 6) << 1;

    // cp.async destination offsets (stage-relative, bytes), j = 0..3
    uint32_t adst[4];
    uint32_t asrcoff[4];   // byte offset within a chunk row-slice
#pragma unroll
    for (int j = 0; j < 4; j++) {
        int cu4 = le + j * 8;
        int q = (cu4 & 3) * 4;
        adst[j] = (uint32_t)((cu4 >> 2) * 2048 + lr * 64 + ((q ^ lsw) << 2));
        asrcoff[j] = (uint32_t)(cu4 * 16);
    }

    // ldmatrix address invariants
    uint32_t aterm, aswz;
    {
        int rowA = wm * 16 + lane15;
        aterm = (uint32_t)rowA * 64u;
        aswz = (uint32_t)((rowA & 6) >> 1);
    }
    uint32_t wterm[2], wswz[2];
#pragma unroll
    for (int ntp = 0; ntp < 2; ntp++) {
        int rowW = (2 * ntp + laneq) * 8 + lane7;
        wterm[ntp] = (uint32_t)rowW * 64u;
        wswz[ntp] = (uint32_t)((rowW & 6) >> 1);
    }

#define AISSUE(kc_, p_) do {                                                 \
        const char* base_ = abytes + (size_t)(kc_) * 512;                    \
        uint32_t db_ = sA0 + (uint32_t)(p_) * 16384u;                        \
        CP_ASYNC16(db_ + adst[0], base_ + asrcoff[0]);                       \
        CP_ASYNC16(db_ + adst[1], base_ + asrcoff[1]);                       \
        CP_ASYNC16(db_ + adst[2], base_ + asrcoff[2]);                       \
        CP_ASYNC16(db_ + adst[3], base_ + asrcoff[3]);                       \
        CP_COMMIT();                                                         \
    } while (0)

#define LOADFRAG(buf, kc_, jj_, abase_) do {                                  \
        int j16_ = (jj_) * 4 + wk;                                            \
        int s_ = j16_ >> 1, h_ = j16_ & 1;                                    \
        uint32_t slabA_ = (abase_) + (uint32_t)s_ * 2048u;                    \
        uint32_t slabW_ = sW0 + (uint32_t)((kc_) * 8 + s_ + 32) * 2048u;      \
        ldsm_x4(af[buf][0], af[buf][1], af[buf][2], af[buf][3],               \
                slabA_ + aterm + ((((uint32_t)(2 * h_ + laneq)) ^ aswz) << 4));\
        uint32_t segw_ = (uint32_t)(2 * h_ + laneh);                          \
        ldsm_x4(bfA[buf][0][0], bfA[buf][0][1], bfA[buf][1][0], bfA[buf][1][1],\
                slabW_ + wterm[0] + ((segw_ ^ wswz[0]) << 4));                \
        ldsm_x4(bfA[buf][2][0], bfA[buf][2][1], bfA[buf][3][0], bfA[buf][3][1],\
                slabW_ + wterm[1] + ((segw_ ^ wswz[1]) << 4));                \
    } while (0)

    // xproj prefetch for t = 0
    float xp0, xp1, xp2, xp3;
    {
        const float* xp = g_xproj + ((size_t)(cb * T_ + 0)) * G4 + uu;
        xp0 = xp[0]; xp1 = xp[1024]; xp2 = xp[2048]; xp3 = xp[3072];
    }

    for (int t = 0; t < T_; t++) {
        const __nv_bfloat16* Abase =
            (t == 0) ? (g_A0 + lr * KA)
                     : (g_A2 + ((size_t)(lr * T_ + (t - 1))) * KA);
        const char* abytes = (const char*)Abase;

        float acc[4][4];
#pragma unroll
        for (int i = 0; i < 4; i++)
#pragma unroll
            for (int q = 0; q < 4; q++) acc[i][q] = 0.f;

        // stage chunk 0 into buffer 0
        AISSUE(0, 0);

        for (int kc = 0; kc < 8; kc++) {
            int p = kc & 1;
            CP_WAIT0();
            __syncthreads();
            if (kc + 1 < 8) AISSUE(kc + 1, p ^ 1);

            uint32_t abase = sA0 + (uint32_t)p * 16384u;
            uint32_t af[2][4], bfA[2][4][2];
            LOADFRAG(0, kc, 0, abase);
#pragma unroll
            for (int jj = 0; jj < 4; jj++) {
                if (jj < 3) LOADFRAG((jj + 1) & 1, kc, jj + 1, abase);
                int cur = jj & 1;
                if (kc < 4) {
                    int j16 = jj * 4 + wk;
                    int s = j16 >> 1, h = j16 & 1;
                    uint32_t slabW0b = sW0 + (uint32_t)(kc * 8 + s) * 2048u;
                    uint32_t segw = (uint32_t)(2 * h + laneh);
                    uint32_t bfB[4][2];
                    ldsm_x4(bfB[0][0], bfB[0][1], bfB[1][0], bfB[1][1],
                            slabW0b + wterm[0] + ((segw ^ wswz[0]) << 4));
                    ldsm_x4(bfB[2][0], bfB[2][1], bfB[3][0], bfB[3][1],
                            slabW0b + wterm[1] + ((segw ^ wswz[1]) << 4));
#pragma unroll
                    for (int nt = 0; nt < 4; nt++)
                        mma_bf16(acc[nt], af[cur], bfA[cur][nt]);
#pragma unroll
                    for (int nt = 0; nt < 4; nt++)
                        mma_bf16(acc[nt], af[cur], bfB[nt]);
                } else {
#pragma unroll
                    for (int nt = 0; nt < 4; nt++)
                        mma_bf16(acc[nt], af[cur], bfA[cur][nt]);
                }
            }
        }
        __syncthreads();   // all ldsm reads of sA done before Csum overlay writes

#pragma unroll
        for (int nt = 0; nt < 4; nt++) {
#pragma unroll
            for (int i2 = 0; i2 < 2; i2++) {
                int m = wm * 16 + g + i2 * 8;
                int n = nt * 8 + 2 * tig;
                Csum[(wk * 32 + m) * 33 + n]     = acc[nt][i2 * 2];
                Csum[(wk * 32 + m) * 33 + n + 1] = acc[nt][i2 * 2 + 1];
            }
        }
        __syncthreads();

        {
            float gate[4];
#pragma unroll
            for (int g4 = 0; g4 < 4; g4++) {
                int n = g4 * 8 + cu;
                gate[g4] = Csum[(0 * 32 + cb) * 33 + n] + Csum[(1 * 32 + cb) * 33 + n]
                         + Csum[(2 * 32 + cb) * 33 + n] + Csum[(3 * 32 + cb) * 33 + n];
            }
            gate[0] += xp0; gate[1] += xp1; gate[2] += xp2; gate[3] += xp3;
            float cn = sigmoidf_(gate[1]) * creg + sigmoidf_(gate[0]) * tanhf(gate[2]);
            float hn = sigmoidf_(gate[3]) * tanhf(cn);
            creg = cn;
            __nv_bfloat16 hi = __float2bfloat16(hn);
            __nv_bfloat16 lo = __float2bfloat16(hn - __bfloat162float(hi));
            __nv_bfloat16* r = g_A2 + ((size_t)(cb * T_ + t)) * KA;
            r[uu] = hi; r[uu + 1024] = lo;
        }
        if (t + 1 < T_) {
            const float* xp = g_xproj + ((size_t)(cb * T_ + t + 1)) * G4 + uu;
            xp0 = xp[0]; xp1 = xp[1024]; xp2 = xp[2048]; xp3 = xp[3072];
        }
        GRIDBAR();
    }
#undef GRIDBAR
#undef LOADFRAG
#undef AISSUE
}

// ---------------- launcher ---------------------------------------------------------
extern "C" void kernel_launch(void* const* d_in, const int* in_sizes, int n_in,
                              void* d_out, int out_size) {
    const float* features = (const float*)d_in[0];
    const int*   reports  = (const int*)d_in[1];
    const float* fc_W     = (const float*)d_in[2];
    const float* fc_b     = (const float*)d_in[3];
    const float* emb      = (const float*)d_in[4];
    const float* W_ih     = (const float*)d_in[5];
    const float* W_hh     = (const float*)d_in[6];
    const float* b_ih     = (const float*)d_in[7];
    const float* b_hh     = (const float*)d_in[8];
    const float* Wv       = (const float*)d_in[9];
    const float* bv       = (const float*)d_in[10];
    float* out = (float*)d_out;

    float *xproj_p, *bsum_p;
    __nv_bfloat16 *A2_p, *B2_p, *E2_p, *I2_p;
    int* idx_p;
    cudaGetSymbolAddress((void**)&xproj_p,  g_xproj);
    cudaGetSymbolAddress((void**)&bsum_p,   g_bsum);
    cudaGetSymbolAddress((void**)&idx_p,    g_idx);
    cudaGetSymbolAddress((void**)&A2_p,     g_A2);
    cudaGetSymbolAddress((void**)&B2_p,     g_B2);
    cudaGetSymbolAddress((void**)&E2_p,     g_E2);
    cudaGetSymbolAddress((void**)&I2_p,     g_I2);

    cudaFuncSetAttribute(lstm_persistent,
                         cudaFuncAttributeMaxDynamicSharedMemorySize, 229376);

    // #1: fused bf16 splits
    int convN = NW_ + NWH + NEM + NWI;
    conv_all_kernel<<<(convN + 255) / 256, 256>>>(Wv, W_hh, emb, W_ih);

    // #2: pooling + prep
    pool_prep_kernel<<<273, 256>>>(features, reports, b_ih, b_hh);

    // #3: xproj = emb[idx] @ W_ih^T + bsum
    mma_gemm_nt<KE, KE, true><<<dim3((B_ * T_) / 128, G4 / 128), 256>>>(
        E2_p, I2_p, bsum_p, xproj_p, G4, idx_p);

    // #4: persistent tensor-core LSTM
    lstm_persistent<<<NBLK, 256, 229376>>>(fc_W, fc_b);

    // #5: output projection (A stored [hi|lo], B [hi|lo|hi])
    mma_gemm_nt<KC, KA, false><<<dim3((B_ * T_) / 128, V_ / 128), 256>>>(
        A2_p, B2_p, bv, out, V_, nullptr);
}

// round 12
// speedup vs baseline: 1.6502x; 1.0123x over previous
#include <cuda_runtime.h>
#include <cuda_bf16.h>
#include <math.h>
#include <stdint.h>

#define B_  32
#define T_  128
#define V_  16000
#define E_  512
#define H_  1024
#define F_  2048
#define G4  4096   // 4*H
#define KC  3072   // 3*H contraction length (B-side [hi|lo|hi])
#define KA  2048   // A-side storage [hi|lo]
#define KE  1536   // 3*E (xproj, both sides stored full)
#define NBLK 128   // persistent LSTM blocks

// ---------------- scratch (device globals: no allocation allowed) ----------
__device__ float g_pooled[B_ * F_];
__device__ float g_bsum[G4];
__device__ int   g_idx[B_ * T_];
__device__ float g_xproj[(size_t)B_ * T_ * G4];        // 67 MB
__device__ __nv_bfloat16 g_A2[(size_t)B_ * T_ * KA];   // 16.8 MB [hi|lo]
__device__ __nv_bfloat16 g_B2[(size_t)V_ * KC];        // 98 MB  [hi|lo|hi]
__device__ __nv_bfloat16 g_W2[(size_t)G4 * KC];        // 25 MB  [hi|lo|hi]
__device__ __nv_bfloat16 g_E2[(size_t)V_ * KE];        // 49 MB  [hi|hi|lo]
__device__ __nv_bfloat16 g_I2[(size_t)G4 * KE];        // 12.6MB [hi|lo|hi]
__device__ __nv_bfloat16 g_A0[B_ * KA];                // h0 split [hi|lo]
__device__ unsigned int  g_barcnt;

// ---------------- cp.async helpers ---------------------------------------------
#define CP_ASYNC16(dst, src) \
    asm volatile("cp.async.cg.shared.global [%0], [%1], 16;" \
                 :: "r"((uint32_t)(dst)), "l"(src))
#define CP_COMMIT() asm volatile("cp.async.commit_group;" ::: "memory")
#define CP_WAIT0()  asm volatile("cp.async.wait_group 0;" ::: "memory")
#define CP_WAIT1()  asm volatile("cp.async.wait_group 1;" ::: "memory")

// ---------------- fused pre kernel (launch #1): conv splits + pool + prep ------
#define NW_  (V_ * H_)
#define NWH  (G4 * H_)
#define NEM  (V_ * E_)
#define NWI  (G4 * E_)
#define CONVTOT (NW_ + NWH + NEM + NWI)
#define CONVBLK ((CONVTOT + 255) / 256)
__global__ void pre_kernel(const float* __restrict__ Wv,
                           const float* __restrict__ W_hh,
                           const float* __restrict__ emb,
                           const float* __restrict__ W_ih,
                           const float* __restrict__ feat,
                           const int* __restrict__ reports,
                           const float* __restrict__ b_ih,
                           const float* __restrict__ b_hh) {
    int bid = blockIdx.x, tid = threadIdx.x;
    if (bid < CONVBLK) {
        int i = bid * 256 + tid;
        const float* S;
        __nv_bfloat16* D;
        int li, sec, style;
        if (i < NW_) {
            S = Wv; D = g_B2; li = i; sec = 1024; style = 1;
        } else if (i < NW_ + NWH) {
            S = W_hh; D = g_W2; li = i - NW_; sec = 1024; style = 1;
        } else if (i < NW_ + NWH + NEM) {
            S = emb; D = g_E2; li = i - NW_ - NWH; sec = 512; style = 0;
        } else if (i < CONVTOT) {
            S = W_ih; D = g_I2; li = i - NW_ - NWH - NEM; sec = 512; style = 1;
        } else return;
        float x = S[li];
        int m = (sec == 1024) ? (li >> 10) : (li >> 9);
        int k = li & (sec - 1);
        __nv_bfloat16 hi = __float2bfloat16(x);
        __nv_bfloat16 lo = __float2bfloat16(x - __bfloat162float(hi));
        __nv_bfloat16* r = D + (size_t)m * (3 * sec);
        if (style == 0) { r[k] = hi; r[k + sec] = hi; r[k + 2 * sec] = lo; }
        else            { r[k] = hi; r[k + sec] = lo; r[k + 2 * sec] = hi; }
    } else if (bid < CONVBLK + 256) {
        int i = (bid - CONVBLK) * 256 + tid;
        const float* p = feat + (size_t)i * 49;
        float s = 0.f;
#pragma unroll
        for (int k = 0; k < 49; k++) s += p[k];
        g_pooled[i] = s * (1.0f / 49.0f);
    } else {
        int j = (bid - CONVBLK - 256) * 256 + tid;
        if (j == 0) g_barcnt = 0u;
        if (j < G4) g_bsum[j] = b_ih[j] + b_hh[j];
        if (j < B_ * T_) g_idx[j] = ((j & (T_ - 1)) == 0) ? 1 : reports[j - 1];
    }
}

// ---------------- mma / ldmatrix helpers ----------------------------------------
__device__ __forceinline__ uint32_t smem_u32(const void* p) {
    uint32_t a;
    asm("{ .reg .u64 t; cvta.to.shared.u64 t, %1; cvt.u32.u64 %0, t; }"
        : "=r"(a) : "l"(p));
    return a;
}
__device__ __forceinline__ void mma_bf16(float* d, const uint32_t* a,
                                         const uint32_t* b) {
    asm volatile(
        "mma.sync.aligned.m16n8k16.row.col.f32.bf16.bf16.f32 "
        "{%0,%1,%2,%3}, {%4,%5,%6,%7}, {%8,%9}, {%0,%1,%2,%3};"
        : "+f"(d[0]), "+f"(d[1]), "+f"(d[2]), "+f"(d[3])
        : "r"(a[0]), "r"(a[1]), "r"(a[2]), "r"(a[3]), "r"(b[0]), "r"(b[1]));
}
__device__ __forceinline__ void ldsm_x4(uint32_t& r0, uint32_t& r1,
                                        uint32_t& r2, uint32_t& r3,
                                        uint32_t addr) {
    asm volatile("ldmatrix.sync.aligned.m8n8.x4.shared.b16 {%0,%1,%2,%3}, [%4];"
                 : "=r"(r0), "=r"(r1), "=r"(r2), "=r"(r3) : "r"(addr));
}
__device__ __forceinline__ float sigmoidf_(float x) {
    return 1.f / (1.f + expf(-x));
}

// ---------------- 128x128 bf16 mma GEMM (cp.async 3-stage, ldmatrix) -----------
template <int KTOT, int AK, bool GATHER>
__global__ void __launch_bounds__(256, 2)
mma_gemm_nt(const __nv_bfloat16* __restrict__ A2,
            const __nv_bfloat16* __restrict__ B2,
            const float* __restrict__ bias,
            float* __restrict__ C, int ncols,
            const int* __restrict__ ridx) {
    __shared__ uint32_t sA[3][128 * 16];
    __shared__ uint32_t sB[3][128 * 16];

    const int NK = KTOT / 32;
    const int TH = (KTOT - AK) / 32;
    int tid = threadIdx.x;
    int lane = tid & 31, w = tid >> 5;
    int g = lane >> 2, tig = lane & 3;
    int wm = w >> 2, wn = w & 3;
    int laneq = lane >> 4;
    int laneh = (lane >> 3) & 1;
    int lane15 = lane & 15, lane7 = lane & 7;

    int m0 = blockIdx.x * 128;
    int n0 = blockIdx.y * 128;

    uint32_t sA0 = smem_u32(sA), sB0 = smem_u32(sB);

    int lrow = tid >> 1;
    int lhalf = tid & 1;
    int ar = GATHER ? ridx[m0 + lrow] : (m0 + lrow);
    const char* pa = (const char*)((const uint4*)(A2 + (size_t)ar * AK) + lhalf * 2);
    const char* pb = (const char*)((const uint4*)(B2 + (size_t)(n0 + lrow) * KTOT) + lhalf * 2);
    int sw = lrow & 6;
    uint32_t st0 = (uint32_t)(((lrow << 4) + (((lhalf * 4 + 0) ^ sw) << 1)) << 2);
    uint32_t st1 = (uint32_t)(((lrow << 4) + (((lhalf * 4 + 2) ^ sw) << 1)) << 2);

    uint32_t aterm[4], aswz[4];
#pragma unroll
    for (int mt = 0; mt < 4; mt++) {
        int rowA = wm * 64 + mt * 16 + lane15;
        aterm[mt] = (uint32_t)rowA * 64u;
        aswz[mt] = (uint32_t)((rowA & 6) >> 1);
    }
    uint32_t bterm[2], bswz[2];
#pragma unroll
    for (int ntp = 0; ntp < 2; ntp++) {
        int rowB = wn * 32 + (2 * ntp + laneq) * 8 + lane7;
        bterm[ntp] = (uint32_t)rowB * 64u;
        bswz[ntp] = (uint32_t)((rowB & 6) >> 1);
    }

    float acc[4][4][4];
#pragma unroll
    for (int i = 0; i < 4; i++)
#pragma unroll
        for (int j = 0; j < 4; j++)
#pragma unroll
            for (int q = 0; q < 4; q++) acc[i][j][q] = 0.f;

#define AIDX(kn_) ((TH == 0) ? (kn_) : (((kn_) < TH) ? (kn_) : (kn_) - TH))
#define GISSUE(kn_, st_) do {                                                \
        int akc_ = AIDX(kn_);                                                \
        const char* pa_ = pa + (size_t)akc_ * 64;                            \
        const char* pb_ = pb + (size_t)(kn_) * 64;                           \
        uint32_t ab_ = sA0 + (uint32_t)(st_) * 8192u;                        \
        uint32_t bb_ = sB0 + (uint32_t)(st_) * 8192u;                        \
        CP_ASYNC16(ab_ + st0, pa_);                                          \
        CP_ASYNC16(ab_ + st1, pa_ + 16);                                     \
        CP_ASYNC16(bb_ + st0, pb_);                                          \
        CP_ASYNC16(bb_ + st1, pb_ + 16);                                     \
        CP_COMMIT();                                                         \
    } while (0)

    GISSUE(0, 0);
    GISSUE(1, 1);

    for (int kc = 0; kc < NK; kc++) {
        int st = kc % 3;
        if (kc + 1 < NK) { CP_WAIT1(); } else { CP_WAIT0(); }
        __syncthreads();
        if (kc + 2 < NK) GISSUE(kc + 2, (kc + 2) % 3);

        uint32_t abase = sA0 + (uint32_t)st * 8192u;
        uint32_t bbase = sB0 + (uint32_t)st * 8192u;
#pragma unroll
        for (int ks = 0; ks < 2; ks++) {
            uint32_t bf[4][2];
            {
                uint32_t segb = (uint32_t)(2 * ks + laneh);
                ldsm_x4(bf[0][0], bf[0][1], bf[1][0], bf[1][1],
                        bbase + bterm[0] + (((segb ^ bswz[0])) << 4));
                ldsm_x4(bf[2][0], bf[2][1], bf[3][0], bf[3][1],
                        bbase + bterm[1] + (((segb ^ bswz[1])) << 4));
            }
            uint32_t sega = (uint32_t)(2 * ks + laneq);
#pragma unroll
            for (int mt = 0; mt < 4; mt++) {
                uint32_t af[4];
                ldsm_x4(af[0], af[1], af[2], af[3],
                        abase + aterm[mt] + (((sega ^ aswz[mt])) << 4));
#pragma unroll
                for (int nt = 0; nt < 4; nt++)
                    mma_bf16(acc[mt][nt], af, bf[nt]);
            }
        }
    }
#undef GISSUE
#undef AIDX

#pragma unroll
    for (int mt = 0; mt < 4; mt++) {
#pragma unroll
        for (int i2 = 0; i2 < 2; i2++) {
            int row = m0 + wm * 64 + mt * 16 + g + i2 * 8;
            float* crow = C + (size_t)row * ncols;
#pragma unroll
            for (int nt = 0; nt < 4; nt++) {
                int col = n0 + wn * 32 + nt * 8 + 2 * tig;
                float b0 = __ldg(&bias[col]);
                float b1 = __ldg(&bias[col + 1]);
                crow[col]     = acc[mt][nt][i2 * 2]     + b0;
                crow[col + 1] = acc[mt][nt][i2 * 2 + 1] + b1;
            }
        }
    }
}

// ---------------- persistent tensor-core LSTM (launch #3) -----------------------
// W smem deduped to [hi|lo] (64 slabs, 128KB); slabW = (kc*8+s)^32.
// 3-stage cp.async A staging; dual accumulators halve HMMA RAW chain.
__global__ void __launch_bounds__(256, 1)
lstm_persistent(const float* __restrict__ fc_W, const float* __restrict__ fc_b) {
    extern __shared__ char smem[];
    uint32_t* sW = (uint32_t*)smem;                    // 64 slabs x 2048B = 128KB
    uint32_t* sA = (uint32_t*)(smem + 131072);         // 3 x 16KB
    float*  Csum = (float*)(smem + 131072);            // overlay (33.8KB <= 48KB)

    int tid = threadIdx.x;
    int lane = tid & 31, w = tid >> 5;
    int g = lane >> 2, tig = lane & 3;
    int wm = w >> 2, wk = w & 3;
    int u0 = blockIdx.x * 8;
    int laneq = lane >> 4;
    int laneh = (lane >> 3) & 1;
    int lane15 = lane & 15, lane7 = lane & 7;

    uint32_t sW0 = smem_u32(sW), sA0 = smem_u32(sA);

    // ---- one-time: stage W slice [32 rows x 2048 ([hi|lo] only)] ----
    {
        int r = tid >> 3, e = tid & 7;
        int grow = ((r >> 3) << 10) + u0 + (r & 7);
        const uint4* wrow = (const uint4*)(g_W2 + (size_t)grow * KC);
        int sw = (r & 6) << 1;
#pragma unroll 4
        for (int j = 0; j < 32; j++) {
            int idx = e + j * 8;              // 0..255 uint4 = 2048 cols
            uint4 v = wrow[idx];
            int s = idx >> 2, q = (idx & 3) * 4;
            *(uint4*)&sW[s * 512 + r * 16 + (q ^ sw)] = v;
        }
    }

    // ---- fc prologue: this block's 16 init columns (8 h + 8 c) ----
    int cb = tid >> 3, cu = tid & 7;
    int uu = u0 + cu;
    float acch = fc_b[uu], accc = fc_b[H_ + uu];
    {
        const float4* pp  = (const float4*)(g_pooled + cb * F_);
        const float4* pwh = (const float4*)(fc_W + (size_t)uu * F_);
        const float4* pwc = (const float4*)(fc_W + (size_t)(H_ + uu) * F_);
#pragma unroll 4
        for (int k = 0; k < F_ / 4; k++) {
            float4 p = pp[k], a = pwh[k], b = pwc[k];
            acch += p.x * a.x + p.y * a.y + p.z * a.z + p.w * a.w;
            accc += p.x * b.x + p.y * b.y + p.z * b.z + p.w * b.w;
        }
    }
    float creg = accc;
    {
        __nv_bfloat16 hi = __float2bfloat16(acch);
        __nv_bfloat16 lo = __float2bfloat16(acch - __bfloat162float(hi));
        __nv_bfloat16* r = g_A0 + cb * KA;
        r[uu] = hi; r[uu + 1024] = lo;
    }

    unsigned epoch = 0;
    unsigned long long barp;
    asm("cvta.global.u64 %0, %1;" : "=l"(barp) : "l"(&g_barcnt));
#define GRIDBAR() do {                                                       \
        __syncthreads();                                                     \
        epoch++;                                                             \
        if (tid == 0) {                                                      \
            asm volatile("red.release.gpu.global.add.u32 [%0], %1;"          \
                         :: "l"(barp), "r"(1u) : "memory");                  \
            unsigned v_;                                                     \
            do {                                                             \
                asm volatile("ld.acquire.gpu.global.u32 %0, [%1];"           \
                             : "=r"(v_) : "l"(barp) : "memory");             \
            } while (v_ < epoch * (unsigned)NBLK);                           \
        }                                                                    \
        __syncthreads();                                                     \
    } while (0)

    GRIDBAR();

    int lr = tid >> 3, le = tid & 7;
    int lsw = (lr & 6) << 1;

    // cp.async destination offsets (stage-relative, bytes), j = 0..3
    uint32_t adst[4];
    uint32_t asrcoff[4];
#pragma unroll
    for (int j = 0; j < 4; j++) {
        int cu4 = le + j * 8;
        int q = (cu4 & 3) * 4;
        adst[j] = (uint32_t)((cu4 >> 2) * 2048 + lr * 64 + ((q ^ lsw) << 2));
        asrcoff[j] = (uint32_t)(cu4 * 16);
    }

    // ldmatrix address invariants
    uint32_t aterm, aswz;
    {
        int rowA = wm * 16 + lane15;
        aterm = (uint32_t)rowA * 64u;
        aswz = (uint32_t)((rowA & 6) >> 1);
    }
    uint32_t wterm[2], wswz[2];
#pragma unroll
    for (int ntp = 0; ntp < 2; ntp++) {
        int rowW = (2 * ntp + laneq) * 8 + lane7;
        wterm[ntp] = (uint32_t)rowW * 64u;
        wswz[ntp] = (uint32_t)((rowW & 6) >> 1);
    }

#define AISSUE(kc_, p_) do {                                                 \
        const char* base_ = abytes + (size_t)(kc_) * 512;                    \
        uint32_t db_ = sA0 + (uint32_t)(p_) * 16384u;                        \
        CP_ASYNC16(db_ + adst[0], base_ + asrcoff[0]);                       \
        CP_ASYNC16(db_ + adst[1], base_ + asrcoff[1]);                       \
        CP_ASYNC16(db_ + adst[2], base_ + asrcoff[2]);                       \
        CP_ASYNC16(db_ + adst[3], base_ + asrcoff[3]);                       \
        CP_COMMIT();                                                         \
    } while (0)

// slabW index: (kc*8+s) ^ 32  — A-hi slabs hit W-lo (32..63), A-lo hit W-hi (0..31)
#define LOADFRAG(buf, kc_, jj_, abase_) do {                                  \
        int j16_ = (jj_) * 4 + wk;                                            \
        int s_ = j16_ >> 1, h_ = j16_ & 1;                                    \
        uint32_t slabA_ = (abase_) + (uint32_t)s_ * 2048u;                    \
        uint32_t slabW_ = sW0 + (uint32_t)(((kc_) * 8 + s_) ^ 32) * 2048u;    \
        ldsm_x4(af[buf][0], af[buf][1], af[buf][2], af[buf][3],               \
                slabA_ + aterm + ((((uint32_t)(2 * h_ + laneq)) ^ aswz) << 4));\
        uint32_t segw_ = (uint32_t)(2 * h_ + laneh);                          \
        ldsm_x4(bfA[buf][0][0], bfA[buf][0][1], bfA[buf][1][0], bfA[buf][1][1],\
                slabW_ + wterm[0] + ((segw_ ^ wswz[0]) << 4));                \
        ldsm_x4(bfA[buf][2][0], bfA[buf][2][1], bfA[buf][3][0], bfA[buf][3][1],\
                slabW_ + wterm[1] + ((segw_ ^ wswz[1]) << 4));                \
    } while (0)

    // xproj prefetch for t = 0
    float xp0, xp1, xp2, xp3;
    {
        const float* xp = g_xproj + ((size_t)(cb * T_ + 0)) * G4 + uu;
        xp0 = xp[0]; xp1 = xp[1024]; xp2 = xp[2048]; xp3 = xp[3072];
    }

    for (int t = 0; t < T_; t++) {
        const __nv_bfloat16* Abase =
            (t == 0) ? (g_A0 + lr * KA)
                     : (g_A2 + ((size_t)(lr * T_ + (t - 1))) * KA);
        const char* abytes = (const char*)Abase;

        float acc0[4][4], acc1[4][4];
#pragma unroll
        for (int i = 0; i < 4; i++)
#pragma unroll
            for (int q = 0; q < 4; q++) { acc0[i][q] = 0.f; acc1[i][q] = 0.f; }

        // 3-stage prologue
        AISSUE(0, 0);
        AISSUE(1, 1);

        for (int kc = 0; kc < 8; kc++) {
            int p = kc % 3;
            if (kc + 1 < 8) { CP_WAIT1(); } else { CP_WAIT0(); }
            __syncthreads();
            if (kc + 2 < 8) AISSUE(kc + 2, (kc + 2) % 3);

            uint32_t abase = sA0 + (uint32_t)p * 16384u;
            uint32_t af[2][4], bfA[2][4][2];
            LOADFRAG(0, kc, 0, abase);
#pragma unroll
            for (int jj = 0; jj < 4; jj++) {
                if (jj < 3) LOADFRAG((jj + 1) & 1, kc, jj + 1, abase);
                int cur = jj & 1;
                float (*accp)[4] = (jj & 1) ? acc1 : acc0;
                if (kc < 4) {
                    int j16 = jj * 4 + wk;
                    int s = j16 >> 1, h = j16 & 1;
                    uint32_t slabW0b = sW0 + (uint32_t)(kc * 8 + s) * 2048u;
                    uint32_t segw = (uint32_t)(2 * h + laneh);
                    uint32_t bfB[4][2];
                    ldsm_x4(bfB[0][0], bfB[0][1], bfB[1][0], bfB[1][1],
                            slabW0b + wterm[0] + ((segw ^ wswz[0]) << 4));
                    ldsm_x4(bfB[2][0], bfB[2][1], bfB[3][0], bfB[3][1],
                            slabW0b + wterm[1] + ((segw ^ wswz[1]) << 4));
#pragma unroll
                    for (int nt = 0; nt < 4; nt++)
                        mma_bf16(accp[nt], af[cur], bfA[cur][nt]);
#pragma unroll
                    for (int nt = 0; nt < 4; nt++)
                        mma_bf16(accp[nt], af[cur], bfB[nt]);
                } else {
#pragma unroll
                    for (int nt = 0; nt < 4; nt++)
                        mma_bf16(accp[nt], af[cur], bfA[cur][nt]);
                }
            }
        }
        __syncthreads();   // all ldsm reads of sA done before Csum overlay writes

#pragma unroll
        for (int nt = 0; nt < 4; nt++) {
#pragma unroll
            for (int i2 = 0; i2 < 2; i2++) {
                int m = wm * 16 + g + i2 * 8;
                int n = nt * 8 + 2 * tig;
                Csum[(wk * 32 + m) * 33 + n]     = acc0[nt][i2 * 2]     + acc1[nt][i2 * 2];
                Csum[(wk * 32 + m) * 33 + n + 1] = acc0[nt][i2 * 2 + 1] + acc1[nt][i2 * 2 + 1];
            }
        }
        __syncthreads();

        {
            float gate[4];
#pragma unroll
            for (int g4 = 0; g4 < 4; g4++) {
                int n = g4 * 8 + cu;
                gate[g4] = Csum[(0 * 32 + cb) * 33 + n] + Csum[(1 * 32 + cb) * 33 + n]
                         + Csum[(2 * 32 + cb) * 33 + n] + Csum[(3 * 32 + cb) * 33 + n];
            }
            gate[0] += xp0; gate[1] += xp1; gate[2] += xp2; gate[3] += xp3;
            float cn = sigmoidf_(gate[1]) * creg + sigmoidf_(gate[0]) * tanhf(gate[2]);
            float hn = sigmoidf_(gate[3]) * tanhf(cn);
            creg = cn;
            __nv_bfloat16 hi = __float2bfloat16(hn);
            __nv_bfloat16 lo = __float2bfloat16(hn - __bfloat162float(hi));
            __nv_bfloat16* r = g_A2 + ((size_t)(cb * T_ + t)) * KA;
            r[uu] = hi; r[uu + 1024] = lo;
        }
        if (t + 1 < T_) {
            const float* xp = g_xproj + ((size_t)(cb * T_ + t + 1)) * G4 + uu;
            xp0 = xp[0]; xp1 = xp[1024]; xp2 = xp[2048]; xp3 = xp[3072];
        }
        GRIDBAR();
    }
#undef GRIDBAR
#undef LOADFRAG
#undef AISSUE
}

// ---------------- launcher ---------------------------------------------------------
extern "C" void kernel_launch(void* const* d_in, const int* in_sizes, int n_in,
                              void* d_out, int out_size) {
    const float* features = (const float*)d_in[0];
    const int*   reports  = (const int*)d_in[1];
    const float* fc_W     = (const float*)d_in[2];
    const float* fc_b     = (const float*)d_in[3];
    const float* emb      = (const float*)d_in[4];
    const float* W_ih     = (const float*)d_in[5];
    const float* W_hh     = (const float*)d_in[6];
    const float* b_ih     = (const float*)d_in[7];
    const float* b_hh     = (const float*)d_in[8];
    const float* Wv       = (const float*)d_in[9];
    const float* bv       = (const float*)d_in[10];
    float* out = (float*)d_out;

    float *xproj_p, *bsum_p;
    __nv_bfloat16 *A2_p, *B2_p, *E2_p, *I2_p;
    int* idx_p;
    cudaGetSymbolAddress((void**)&xproj_p,  g_xproj);
    cudaGetSymbolAddress((void**)&bsum_p,   g_bsum);
    cudaGetSymbolAddress((void**)&idx_p,    g_idx);
    cudaGetSymbolAddress((void**)&A2_p,     g_A2);
    cudaGetSymbolAddress((void**)&B2_p,     g_B2);
    cudaGetSymbolAddress((void**)&E2_p,     g_E2);
    cudaGetSymbolAddress((void**)&I2_p,     g_I2);

    cudaFuncSetAttribute(lstm_persistent,
                         cudaFuncAttributeMaxDynamicSharedMemorySize, 180224);

    // #1: fused pre (conv splits + pooling + prep)
    pre_kernel<<<CONVBLK + 256 + 17, 256>>>(Wv, W_hh, emb, W_ih,
                                            features, reports, b_ih, b_hh);

    // #2: xproj = emb[idx] @ W_ih^T + bsum
    mma_gemm_nt<KE, KE, true><<<dim3((B_ * T_) / 128, G4 / 128), 256>>>(
        E2_p, I2_p, bsum_p, xproj_p, G4, idx_p);

    // #3: persistent tensor-core LSTM
    lstm_persistent<<<NBLK, 256, 180224>>>(fc_W, fc_b);

    // #4: output projection  <-- ncu captures THIS now
    mma_gemm_nt<KC, KA, false><<<dim3((B_ * T_) / 128, V_ / 128), 256>>>(
        A2_p, B2_p, bv, out, V_, nullptr);
}